// round 11
// baseline (speedup 1.0000x reference)
#include <cuda_runtime.h>
#include <cuda_bf16.h>
#include <math.h>
#include <stdint.h>

#define C_CLUST 10
#define D_IN    1024
#define D_H     512
#define D_ATT   256
#define N_CLS   4
#define N_MAX   10000
#define NPAD    128

#define KC 64
#define ROWB 144                            // smem row stride bytes (72 bf16)
#define A_BYTES (128 * ROWB)                // 18432
#define STAGE_BYTES (2 * A_BYTES)           // 36864
#define NSTAGE 3
#define SMEM_SZ (NSTAGE * STAGE_BYTES)      // 110592 (>= 128*129*4 for conv, >= 6KB epilogue)

#define NCONV_W1 320                        // 10 * (1024/128)*(512/128)
#define NCONV    480                        // + 10 * (512/128)*(512/128)
#define GROWS    32                         // rows per gather task

// ---------------- scratch ----------------
__device__ int   g_count[C_CLUST];
__device__ int   g_off[C_CLUST];
__device__ int   g_cursor[C_CLUST];
__device__ int   g_g1s[C_CLUST + 1];
__device__ int   g_g2s[C_CLUST + 1];
__device__ int   g_ng;
__device__ int   g_tb0, g_tb1, g_tb2, g_tb3, g_tb4;   // task boundaries
__device__ int   g_ntask;
__device__ int   g_task;
__device__ int   g_gather_done;
__device__ int   g_conv_done;
__device__ int   g_g1_done[C_CLUST];
__device__ int   g_g2_done[C_CLUST];
__device__ int   g_att_done;
__device__ __nv_bfloat16 g_Xg[(size_t)(N_MAX + NPAD) * D_IN];
__device__ __nv_bfloat16 g_H1[(size_t)(N_MAX + NPAD) * D_H];
__device__ __nv_bfloat16 g_W1t[(size_t)C_CLUST * D_H * D_IN];   // [c][n][k]
__device__ __nv_bfloat16 g_W2t[(size_t)C_CLUST * D_H * D_H];
__device__ float g_pool[C_CLUST * D_H];
__device__ float g_hbuf[C_CLUST * D_H];
__device__ float g_Araw[C_CLUST];

__device__ __forceinline__ int detect64(const void* cid) {
    const int* p = (const int*)cid;
    int allz = 1;
#pragma unroll
    for (int i = 1; i < 32; i += 2) if (p[i] != 0) allz = 0;
    return allz;
}
__device__ __forceinline__ int get_cid(const void* cid, int n, int is64) {
    if (is64) return (int)((const long long*)cid)[n];
    return ((const int*)cid)[n];
}
__device__ __forceinline__ uint32_t smem_u32(const void* p) {
    uint32_t a;
    asm("{ .reg .u64 t; cvta.to.shared.u64 t, %1; cvt.u32.u64 %0, t; }" : "=r"(a) : "l"(p));
    return a;
}
__device__ __forceinline__ void cp16(uint32_t smem, const void* gmem) {
    asm volatile("cp.async.cg.shared.global [%0], [%1], 16;" :: "r"(smem), "l"(gmem));
}
__device__ __forceinline__ void ldsm4(uint32_t& r0, uint32_t& r1, uint32_t& r2, uint32_t& r3,
                                      uint32_t addr) {
    asm volatile("ldmatrix.sync.aligned.m8n8.x4.shared.b16 {%0,%1,%2,%3}, [%4];"
                 : "=r"(r0), "=r"(r1), "=r"(r2), "=r"(r3) : "r"(addr));
}
__device__ __forceinline__ void mma_bf16(float c[4], uint32_t a0, uint32_t a1, uint32_t a2,
                                         uint32_t a3, uint32_t b0, uint32_t b1) {
    asm volatile(
        "mma.sync.aligned.m16n8k16.row.col.f32.bf16.bf16.f32 "
        "{%0,%1,%2,%3}, {%4,%5,%6,%7}, {%8,%9}, {%0,%1,%2,%3};\n"
        : "+f"(c[0]), "+f"(c[1]), "+f"(c[2]), "+f"(c[3])
        : "r"(a0), "r"(a1), "r"(a2), "r"(a3), "r"(b0), "r"(b1));
}
__device__ __forceinline__ int ldacq(const int* p) {
    int v; asm volatile("ld.acquire.gpu.s32 %0, [%1];" : "=r"(v) : "l"(p)); return v;
}
#define SPIN_WAIT(cond) do {                      \
    int _sl = 64;                                 \
    while (cond) {                                \
        __nanosleep(_sl);                         \
        if (_sl < 2048) _sl <<= 1;                \
    }                                             \
} while (0)

// ---------------- prep kernels ----------------
__global__ void k_reset() {
    int t = threadIdx.x;   // 512
    for (int i = t; i < C_CLUST * D_H; i += 512) g_pool[i] = 0.f;
    if (t < C_CLUST) {
        g_count[t] = 0; g_cursor[t] = 0; g_g1_done[t] = 0; g_g2_done[t] = 0;
    }
    if (t == 0) { g_task = 0; g_conv_done = 0; g_gather_done = 0; g_att_done = 0; }
}

__global__ void k_count(const void* __restrict__ cid, int n) {
    __shared__ int s[C_CLUST];
    int t = threadIdx.x;
    int is64 = detect64(cid);
    if (t < C_CLUST) s[t] = 0;
    __syncthreads();
    int i = blockIdx.x * blockDim.x + t;
    if (i < n) atomicAdd(&s[get_cid(cid, i, is64)], 1);
    __syncthreads();
    if (t < C_CLUST && s[t]) atomicAdd(&g_count[t], s[t]);
}

__global__ void k_offsets(int n) {
    if (threadIdx.x == 0) {
        int o = 0, g1 = 0, g2 = 0;
        for (int c = 0; c < C_CLUST; c++) {
            g_off[c] = o; o += g_count[c];
            int mt = (g_count[c] + 127) >> 7;
            g_g1s[c] = g1; g1 += 4 * mt;
            g_g2s[c] = g2; g2 += 4 * mt;
        }
        g_g1s[C_CLUST] = g1;
        g_g2s[C_CLUST] = g2;
        int ng = (n + GROWS - 1) / GROWS;
        g_ng = ng;
        g_tb0 = ng;
        g_tb1 = ng + NCONV;
        g_tb2 = ng + NCONV + g1;
        g_tb3 = ng + NCONV + g1 + g2;
        g_tb4 = ng + NCONV + g1 + g2 + C_CLUST;
        g_ntask = g_tb4 + 1;
    }
}

// ---------------- gather task: GROWS rows, slot-claim + coalesced bf16 copy ----------------
__device__ void gather_task(const float* __restrict__ x, const void* __restrict__ cid,
                            int n, int base, char* dsm, int tid) {
    int* slot = (int*)dsm;
    if (tid < GROWS) {
        int p = base + tid;
        int s = -1;
        if (p < n) {
            int is64 = detect64(cid);
            int c = get_cid(cid, p, is64);
            s = g_off[c] + atomicAdd(&g_cursor[c], 1);
        }
        slot[tid] = s;
    }
    __syncthreads();
    int r = tid >> 3, q = tid & 7;           // 8 threads per row
    int p = base + r;
    if (p < n) {
        int dst = slot[r];
        const float4* src = (const float4*)(x + (size_t)p * D_IN);
        uint2* d = (uint2*)(g_Xg + (size_t)dst * D_IN);
#pragma unroll 8
        for (int i = 0; i < 32; i++) {
            float4 v = src[i * 8 + q];               // lanes of a warp hit consecutive 16B
            __nv_bfloat162 lo = __floats2bfloat162_rn(v.x, v.y);
            __nv_bfloat162 hi = __floats2bfloat162_rn(v.z, v.w);
            uint2 u;
            u.x = *(uint32_t*)&lo;
            u.y = *(uint32_t*)&hi;
            d[i * 8 + q] = u;
        }
    }
    __threadfence();
    __syncthreads();
    if (tid == 0) atomicAdd(&g_gather_done, 1);
    __syncthreads();
}

// ---------------- conv tile: 128x128 transpose fp32 -> bf16 ----------------
__device__ void conv_tile(const float* __restrict__ src, __nv_bfloat16* __restrict__ dst,
                          int R, int C, int r0, int c0, float* sm, int tid) {
    int r = tid >> 1;
    int cb = (tid & 1) * 64;
    const float* s = src + (size_t)(r0 + r) * C + c0 + cb;
#pragma unroll
    for (int q = 0; q < 16; q++) {
        float4 v = *(const float4*)(s + q * 4);
        float* d = sm + r * 129 + cb + q * 4;
        d[0] = v.x; d[1] = v.y; d[2] = v.z; d[3] = v.w;
    }
    __syncthreads();
#pragma unroll
    for (int q = 0; q < 16; q++) {
        int lin = q * 256 + tid;
        int j = lin >> 5;
        int i4 = (lin & 31) * 4;
        float a0 = sm[(i4 + 0) * 129 + j];
        float a1 = sm[(i4 + 1) * 129 + j];
        float a2 = sm[(i4 + 2) * 129 + j];
        float a3 = sm[(i4 + 3) * 129 + j];
        __nv_bfloat162 lo = __floats2bfloat162_rn(a0, a1);
        __nv_bfloat162 hi = __floats2bfloat162_rn(a2, a3);
        uint2 u;
        u.x = *(uint32_t*)&lo;
        u.y = *(uint32_t*)&hi;
        *(uint2*)(dst + (size_t)(c0 + j) * R + r0 + i4) = u;
    }
    __syncthreads();
}

// ---------------- GEMM tile: 3-stage cp.async pipeline, one sync per chunk ----------------
template <bool POOL>
__device__ __forceinline__ void gemm_tile(
    const __nv_bfloat16* __restrict__ Aglob, const __nv_bfloat16* __restrict__ Wc,
    const float* __restrict__ bias_c, float* __restrict__ pool_c,
    int K, int M, int seg, int m0, int n0, char* dsm, float* s_col, int tid) {

    uint32_t sbase = smem_u32(dsm);
    int lane = tid & 31;
    int w = tid >> 5;
    int wm = w & 1;
    int wn = w >> 1;
    int g = lane >> 2;
    int tig = lane & 3;
    int l7 = lane & 7, l8 = (lane >> 3) & 1, l16 = lane >> 4;

    float acc[4][4][4];
#pragma unroll
    for (int im = 0; im < 4; im++)
#pragma unroll
        for (int in = 0; in < 4; in++)
#pragma unroll
            for (int q = 0; q < 4; q++) acc[im][in][q] = 0.f;

    int ar = tid >> 1;
    int acs = (tid & 1) * 4;
    const __nv_bfloat16* Arow = Aglob + (size_t)(seg + m0 + ar) * K + acs * 8;
    const __nv_bfloat16* Brow = Wc + (size_t)(n0 + ar) * K + acs * 8;
    uint32_t a_sm = ar * ROWB + acs * 16;
    uint32_t b_sm = A_BYTES + a_sm;

    uint32_t a_frag = (uint32_t)(wm * 64 + l7 + 8 * l8) * ROWB + 16 * l16;
    uint32_t b_frag = A_BYTES + (uint32_t)(wn * 32 + l7 + 8 * l8) * ROWB + 16 * l16;

    int nch = K / KC;            // >= 8

    // prologue: stage chunks 0..NSTAGE-2
#pragma unroll
    for (int s = 0; s < NSTAGE - 1; s++) {
        uint32_t st = sbase + s * STAGE_BYTES;
        const __nv_bfloat16* ap = Arow + s * KC;
        const __nv_bfloat16* bp = Brow + s * KC;
#pragma unroll
        for (int q = 0; q < 4; q++) cp16(st + a_sm + q * 16, ap + q * 8);
#pragma unroll
        for (int q = 0; q < 4; q++) cp16(st + b_sm + q * 16, bp + q * 8);
        asm volatile("cp.async.commit_group;" ::: "memory");
    }

    int buf = 0, pf = NSTAGE - 1;       // buffer of current chunk; chunk to prefetch
    for (int c = 0; c < nch; c++) {
        asm volatile("cp.async.wait_group %0;" :: "n"(NSTAGE - 2) : "memory");
        __syncthreads();

        // prefetch chunk c+NSTAGE-1 into the buffer consumed at chunk c-1
        if (pf < nch) {
            uint32_t st = sbase + (pf % NSTAGE) * STAGE_BYTES;
            const __nv_bfloat16* ap = Arow + pf * KC;
            const __nv_bfloat16* bp = Brow + pf * KC;
#pragma unroll
            for (int q = 0; q < 4; q++) cp16(st + a_sm + q * 16, ap + q * 8);
#pragma unroll
            for (int q = 0; q < 4; q++) cp16(st + b_sm + q * 16, bp + q * 8);
        }
        asm volatile("cp.async.commit_group;" ::: "memory");
        pf++;

        uint32_t stb = sbase + buf * STAGE_BYTES;
#pragma unroll
        for (int ks = 0; ks < 4; ks++) {
            uint32_t koff = ks * 32;
            uint32_t bfr[2][4];
#pragma unroll
            for (int p = 0; p < 2; p++)
                ldsm4(bfr[p][0], bfr[p][1], bfr[p][2], bfr[p][3],
                      stb + b_frag + p * (16 * ROWB) + koff);
            uint32_t afr[4][4];
#pragma unroll
            for (int im = 0; im < 4; im++)
                ldsm4(afr[im][0], afr[im][1], afr[im][2], afr[im][3],
                      stb + a_frag + im * (16 * ROWB) + koff);
#pragma unroll
            for (int im = 0; im < 4; im++) {
#pragma unroll
                for (int p = 0; p < 2; p++) {
                    mma_bf16(acc[im][2 * p],     afr[im][0], afr[im][1], afr[im][2], afr[im][3],
                             bfr[p][0], bfr[p][2]);
                    mma_bf16(acc[im][2 * p + 1], afr[im][0], afr[im][1], afr[im][2], afr[im][3],
                             bfr[p][1], bfr[p][3]);
                }
            }
        }
        buf = (buf + 1 == NSTAGE) ? 0 : buf + 1;
    }
    __syncthreads();      // all reads of dsm done before any reuse

    const float* bp = bias_c + n0;

    if (!POOL) {
#pragma unroll
        for (int im = 0; im < 4; im++) {
            int rg = m0 + wm * 64 + im * 16 + g;
            int rg8 = rg + 8;
#pragma unroll
            for (int in = 0; in < 4; in++) {
                int col = wn * 32 + in * 8 + 2 * tig;
                float b0v = bp[col], b1v = bp[col + 1];
                if (rg < M) {
                    __nv_bfloat162 v = __floats2bfloat162_rn(
                        fmaxf(acc[im][in][0] + b0v, 0.f), fmaxf(acc[im][in][1] + b1v, 0.f));
                    *(__nv_bfloat162*)&g_H1[(size_t)(seg + rg) * D_H + n0 + col] = v;
                }
                if (rg8 < M) {
                    __nv_bfloat162 v = __floats2bfloat162_rn(
                        fmaxf(acc[im][in][2] + b0v, 0.f), fmaxf(acc[im][in][3] + b1v, 0.f));
                    *(__nv_bfloat162*)&g_H1[(size_t)(seg + rg8) * D_H + n0 + col] = v;
                }
            }
        }
    } else {
        if (tid < 128) s_col[tid] = 0.f;
        __syncthreads();
#pragma unroll
        for (int in = 0; in < 4; in++) {
            int col = wn * 32 + in * 8 + 2 * tig;
            float b0v = bp[col], b1v = bp[col + 1];
            float px = 0.f, py = 0.f;
#pragma unroll
            for (int im = 0; im < 4; im++) {
                int rg = m0 + wm * 64 + im * 16 + g;
                if (rg < M) {
                    px += fmaxf(acc[im][in][0] + b0v, 0.f);
                    py += fmaxf(acc[im][in][1] + b1v, 0.f);
                }
                if (rg + 8 < M) {
                    px += fmaxf(acc[im][in][2] + b0v, 0.f);
                    py += fmaxf(acc[im][in][3] + b1v, 0.f);
                }
            }
            atomicAdd(&s_col[col], px);
            atomicAdd(&s_col[col + 1], py);
        }
        __syncthreads();
        if (tid < 128) atomicAdd(&pool_c[n0 + tid], s_col[tid]);
    }
}

// ---------------- fc + gated attention for one cluster (256 threads) ----------------
__device__ void fcatt_task(int c, const float* __restrict__ Wfc, const float* __restrict__ bfc,
                           const float* __restrict__ Wa, const float* __restrict__ ba,
                           const float* __restrict__ Wb, const float* __restrict__ bb,
                           const float* __restrict__ Wcs, const float* __restrict__ bcs,
                           char* dsm, int tid) {
    float* ph = (float*)dsm;          // 512
    float* sh = ph + D_H;             // 512
    float* red = sh + D_H;            // 256
    float inv = 1.f / (float)max(g_count[c], 1);
    for (int i = tid; i < D_H; i += 256) ph[i] = g_pool[c * D_H + i] * inv;
    __syncthreads();
#pragma unroll
    for (int jj = 0; jj < 2; jj++) {
        int j = tid + jj * 256;
        float s = 0.f;
#pragma unroll 16
        for (int k = 0; k < D_H; k++) s += ph[k] * Wfc[k * D_H + j];
        float h = fmaxf(s + bfc[j], 0.f);
        sh[j] = h;
        g_hbuf[c * D_H + j] = h;
    }
    __syncthreads();
    float sa = 0.f, sb = 0.f;
#pragma unroll 8
    for (int k = 0; k < D_H; k++) {
        float hv = sh[k];
        sa += hv * Wa[k * D_ATT + tid];
        sb += hv * Wb[k * D_ATT + tid];
    }
    float gate = tanhf(sa + ba[tid]) * (1.f / (1.f + expf(-(sb + bb[tid]))));
    red[tid] = gate * Wcs[tid];
    __syncthreads();
    for (int s = 128; s > 0; s >>= 1) {
        if (tid < s) red[tid] += red[tid + s];
        __syncthreads();
    }
    __threadfence();
    __syncthreads();
    if (tid == 0) {
        g_Araw[c] = red[0] + bcs[0];
        __threadfence();
        atomicAdd(&g_att_done, 1);
    }
    __syncthreads();
}

// ---------------- final task (256 threads) ----------------
__device__ void final_task(const float* __restrict__ Wr, const float* __restrict__ br,
                           const float* __restrict__ Wcls, const float* __restrict__ bcls,
                           float* __restrict__ out, int out_size, char* dsm, int tid) {
    float* A = (float*)dsm;           // 10
    float* hp = A + 16;               // 512
    float* hr = hp + D_H;             // 256
    float* lg = hr + D_ATT;           // 4
    if (tid == 0) {
        float m = -1e30f;
        for (int c = 0; c < C_CLUST; c++) m = fmaxf(m, g_Araw[c]);
        float s = 0.f;
        for (int c = 0; c < C_CLUST; c++) { A[c] = expf(g_Araw[c] - m); s += A[c]; }
        float inv = 1.f / s;
        for (int c = 0; c < C_CLUST; c++) A[c] *= inv;
    }
    __syncthreads();
    for (int i = tid; i < D_H; i += 256) {
        float s = 0.f;
#pragma unroll
        for (int c = 0; c < C_CLUST; c++) s += A[c] * g_hbuf[c * D_H + i];
        hp[i] = s;
    }
    __syncthreads();
    {
        float s = 0.f;
#pragma unroll 8
        for (int k = 0; k < D_H; k++) s += hp[k] * Wr[k * D_ATT + tid];
        hr[tid] = fmaxf(s + br[tid], 0.f);
    }
    __syncthreads();
    if (tid < N_CLS) {
        float s = 0.f;
#pragma unroll 8
        for (int k = 0; k < D_ATT; k++) s += hr[k] * Wcls[k * N_CLS + tid];
        lg[tid] = s + bcls[tid];
    }
    __syncthreads();
    if (tid == 0) {
        float m = lg[0];
        int am = 0;
        for (int i = 1; i < N_CLS; i++) if (lg[i] > m) { m = lg[i]; am = i; }
        float e[N_CLS], s = 0.f;
        for (int i = 0; i < N_CLS; i++) { e[i] = expf(lg[i] - m); s += e[i]; }
        float vals[9];
        for (int i = 0; i < N_CLS; i++) vals[i] = lg[i];
        for (int i = 0; i < N_CLS; i++) vals[4 + i] = e[i] / s;
        vals[8] = (float)am;
        for (int i = 0; i < out_size; i++) out[i] = (i < 9) ? vals[i] : 0.f;
    }
    __syncthreads();
}

// ---------------- persistent mega kernel ----------------
__global__ void __launch_bounds__(256, 2)
k_mega(const float* __restrict__ x, const void* __restrict__ cid, int n,
       const float* __restrict__ W1, const float* __restrict__ W2,
       const float* __restrict__ b1, const float* __restrict__ b2,
       const float* __restrict__ Wfc, const float* __restrict__ bfc,
       const float* __restrict__ Wa, const float* __restrict__ ba,
       const float* __restrict__ Wb, const float* __restrict__ bb,
       const float* __restrict__ Wcs, const float* __restrict__ bcs,
       const float* __restrict__ Wr, const float* __restrict__ br,
       const float* __restrict__ Wcls, const float* __restrict__ bcls,
       float* __restrict__ out, int out_size) {
    extern __shared__ char dsm[];
    __shared__ float s_col[128];
    __shared__ int s_task;
    int tid = threadIdx.x;

    int ng = g_ng;
    int tb0 = g_tb0, tb1 = g_tb1, tb2 = g_tb2, tb3 = g_tb3, tb4 = g_tb4;
    int ntask = g_ntask;

    for (;;) {
        if (tid == 0) s_task = atomicAdd(&g_task, 1);
        __syncthreads();
        int t = s_task;
        if (t >= ntask) break;

        if (t < tb0) {
            gather_task(x, cid, n, t * GROWS, dsm, tid);
        } else if (t < tb1) {
            int tc = t - tb0;
            if (tc < NCONV_W1) {
                int c = tc >> 5, rem = tc & 31;
                conv_tile(W1 + (size_t)c * D_IN * D_H, g_W1t + (size_t)c * D_H * D_IN,
                          D_IN, D_H, (rem >> 2) * 128, (rem & 3) * 128, (float*)dsm, tid);
            } else {
                int t2 = tc - NCONV_W1;
                int c = t2 >> 4, rem = t2 & 15;
                conv_tile(W2 + (size_t)c * D_H * D_H, g_W2t + (size_t)c * D_H * D_H,
                          D_H, D_H, (rem >> 2) * 128, (rem & 3) * 128, (float*)dsm, tid);
            }
            __threadfence();
            __syncthreads();
            if (tid == 0) atomicAdd(&g_conv_done, 1);
        } else if (t < tb2) {
            int t1 = t - tb1;
            int c = 0;
#pragma unroll
            for (int cc = 0; cc < C_CLUST; cc++) if (t1 >= g_g1s[cc + 1]) c = cc + 1;
            int rem = t1 - g_g1s[c];
            int m0 = (rem >> 2) * 128, n0 = (rem & 3) * 128;
            if (tid == 0) {
                SPIN_WAIT(ldacq(&g_gather_done) < ng || ldacq(&g_conv_done) < NCONV);
            }
            __syncthreads();
            gemm_tile<false>(g_Xg, g_W1t + (size_t)c * D_H * D_IN, b1 + c * D_H, nullptr,
                             D_IN, g_count[c], g_off[c], m0, n0, dsm, s_col, tid);
            __threadfence();
            __syncthreads();
            if (tid == 0) atomicAdd(&g_g1_done[c], 1);
        } else if (t < tb3) {
            int t2 = t - tb2;
            int c = 0;
#pragma unroll
            for (int cc = 0; cc < C_CLUST; cc++) if (t2 >= g_g2s[cc + 1]) c = cc + 1;
            int rem = t2 - g_g2s[c];
            int m0 = (rem >> 2) * 128, n0 = (rem & 3) * 128;
            int target = g_g2s[c + 1] - g_g2s[c];
            if (tid == 0) { SPIN_WAIT(ldacq(&g_g1_done[c]) < target); }
            __syncthreads();
            gemm_tile<true>(g_H1, g_W2t + (size_t)c * D_H * D_H, b2 + c * D_H,
                            g_pool + c * D_H, D_H, g_count[c], g_off[c], m0, n0, dsm, s_col, tid);
            __threadfence();
            __syncthreads();
            if (tid == 0) atomicAdd(&g_g2_done[c], 1);
        } else if (t < tb4) {
            int c = t - tb3;
            int target = g_g2s[c + 1] - g_g2s[c];
            if (tid == 0) { SPIN_WAIT(ldacq(&g_g2_done[c]) < target); }
            __syncthreads();
            fcatt_task(c, Wfc, bfc, Wa, ba, Wb, bb, Wcs, bcs, dsm, tid);
        } else {
            if (tid == 0) { SPIN_WAIT(ldacq(&g_att_done) < C_CLUST); }
            __syncthreads();
            final_task(Wr, br, Wcls, bcls, out, out_size, dsm, tid);
        }
        __syncthreads();
    }
}

// ---------------- launch ----------------
extern "C" void kernel_launch(void* const* d_in, const int* in_sizes, int n_in,
                              void* d_out, int out_size) {
    const float* x    = (const float*)d_in[0];
    const void*  cid  = d_in[1];
    const float* W1   = (const float*)d_in[2];
    const float* b1   = (const float*)d_in[3];
    const float* W2   = (const float*)d_in[4];
    const float* b2   = (const float*)d_in[5];
    const float* Wfc  = (const float*)d_in[6];
    const float* bfc  = (const float*)d_in[7];
    const float* Wa   = (const float*)d_in[8];
    const float* ba   = (const float*)d_in[9];
    const float* Wb   = (const float*)d_in[10];
    const float* bb   = (const float*)d_in[11];
    const float* Wc_  = (const float*)d_in[12];
    const float* bc_  = (const float*)d_in[13];
    const float* Wr   = (const float*)d_in[14];
    const float* br   = (const float*)d_in[15];
    const float* Wcls = (const float*)d_in[16];
    const float* bcls = (const float*)d_in[17];

    int n = in_sizes[0] / D_IN;

    static int nsm = 0;
    if (!nsm) {
        cudaDeviceProp prop;
        cudaGetDeviceProperties(&prop, 0);
        nsm = prop.multiProcessorCount;
        cudaFuncSetAttribute(k_mega, cudaFuncAttributeMaxDynamicSharedMemorySize, SMEM_SZ);
    }

    k_reset<<<1, 512>>>();                                     // 1
    k_count<<<(n + 255) / 256, 256>>>(cid, n);                 // 2
    k_offsets<<<1, 32>>>(n);                                   // 3
    k_mega<<<2 * nsm, 256, SMEM_SZ>>>(                         // 4  <- ncu target
        x, cid, n, W1, W2, b1, b2, Wfc, bfc, Wa, ba, Wb, bb,
        Wc_, bc_, Wr, br, Wcls, bcls, (float*)d_out, out_size);
}

// round 13
// speedup vs baseline: 1.3096x; 1.3096x over previous
#include <cuda_runtime.h>
#include <cuda_bf16.h>
#include <math.h>
#include <stdint.h>

#define C_CLUST 10
#define D_IN    1024
#define D_H     512
#define D_ATT   256
#define N_CLS   4
#define N_MAX   10000
#define NPAD    128

#define KC 64
#define ROWB 144                            // smem row stride bytes (72 bf16)
#define A_BYTES (128 * ROWB)                // 18432
#define STAGE_BYTES (2 * A_BYTES)           // 36864
#define SMEM_SZ (2 * STAGE_BYTES)           // 73728 (>= 128*129*4 conv, >= 23KB epilogue)

#define NCONV_W1 320
#define NCONV    480
#define GROWS    32
#define NE1      16                         // fc tasks (32 cols each)
#define NE2      8                          // att tasks (32 cols each)
#define NE3      8                          // rho tasks (32 cols each)

// ---------------- scratch ----------------
__device__ int   g_count[C_CLUST];
__device__ int   g_off[C_CLUST];
__device__ int   g_cursor[C_CLUST];
__device__ int   g_g1s[C_CLUST + 1];
__device__ int   g_g2s[C_CLUST + 1];
__device__ int   g_ng;
__device__ int   g_tb[8];                   // task boundaries
__device__ int   g_ntask;
__device__ int   g_task;
__device__ int   g_gather_done;
__device__ int   g_conv_done;
__device__ int   g_g1_done[C_CLUST];
__device__ int   g_g2_all;
__device__ int   g_e1, g_e2, g_e3;
__device__ __nv_bfloat16 g_Xg[(size_t)(N_MAX + NPAD) * D_IN];
__device__ __nv_bfloat16 g_H1[(size_t)(N_MAX + NPAD) * D_H];
__device__ __nv_bfloat16 g_W1t[(size_t)C_CLUST * D_H * D_IN];
__device__ __nv_bfloat16 g_W2t[(size_t)C_CLUST * D_H * D_H];
__device__ float g_pool[C_CLUST * D_H];
__device__ float g_hbuf[C_CLUST * D_H];
__device__ float g_AccA[C_CLUST];
__device__ float g_hr[D_ATT];

__device__ __forceinline__ int detect64(const void* cid) {
    const int* p = (const int*)cid;
    int allz = 1;
#pragma unroll
    for (int i = 1; i < 32; i += 2) if (p[i] != 0) allz = 0;
    return allz;
}
__device__ __forceinline__ int get_cid(const void* cid, int n, int is64) {
    if (is64) return (int)((const long long*)cid)[n];
    return ((const int*)cid)[n];
}
__device__ __forceinline__ uint32_t smem_u32(const void* p) {
    uint32_t a;
    asm("{ .reg .u64 t; cvta.to.shared.u64 t, %1; cvt.u32.u64 %0, t; }" : "=r"(a) : "l"(p));
    return a;
}
__device__ __forceinline__ void cp16(uint32_t smem, const void* gmem) {
    asm volatile("cp.async.cg.shared.global [%0], [%1], 16;" :: "r"(smem), "l"(gmem));
}
__device__ __forceinline__ void ldsm4(uint32_t& r0, uint32_t& r1, uint32_t& r2, uint32_t& r3,
                                      uint32_t addr) {
    asm volatile("ldmatrix.sync.aligned.m8n8.x4.shared.b16 {%0,%1,%2,%3}, [%4];"
                 : "=r"(r0), "=r"(r1), "=r"(r2), "=r"(r3) : "r"(addr));
}
__device__ __forceinline__ void mma_bf16(float c[4], uint32_t a0, uint32_t a1, uint32_t a2,
                                         uint32_t a3, uint32_t b0, uint32_t b1) {
    asm volatile(
        "mma.sync.aligned.m16n8k16.row.col.f32.bf16.bf16.f32 "
        "{%0,%1,%2,%3}, {%4,%5,%6,%7}, {%8,%9}, {%0,%1,%2,%3};\n"
        : "+f"(c[0]), "+f"(c[1]), "+f"(c[2]), "+f"(c[3])
        : "r"(a0), "r"(a1), "r"(a2), "r"(a3), "r"(b0), "r"(b1));
}
__device__ __forceinline__ int ldacq(const int* p) {
    int v; asm volatile("ld.acquire.gpu.s32 %0, [%1];" : "=r"(v) : "l"(p)); return v;
}
#define SPIN_WAIT(cond) do {                      \
    int _sl = 64;                                 \
    while (cond) {                                \
        __nanosleep(_sl);                         \
        if (_sl < 2048) _sl <<= 1;                \
    }                                             \
} while (0)

// ---------------- prep kernels ----------------
__global__ void k_reset() {
    int t = threadIdx.x;   // 512
    for (int i = t; i < C_CLUST * D_H; i += 512) g_pool[i] = 0.f;
    if (t < C_CLUST) {
        g_count[t] = 0; g_cursor[t] = 0; g_g1_done[t] = 0; g_AccA[t] = 0.f;
    }
    if (t == 0) {
        g_task = 0; g_conv_done = 0; g_gather_done = 0;
        g_g2_all = 0; g_e1 = 0; g_e2 = 0; g_e3 = 0;
    }
}

__global__ void k_count(const void* __restrict__ cid, int n) {
    __shared__ int s[C_CLUST];
    int t = threadIdx.x;
    int is64 = detect64(cid);
    if (t < C_CLUST) s[t] = 0;
    __syncthreads();
    int i = blockIdx.x * blockDim.x + t;
    if (i < n) atomicAdd(&s[get_cid(cid, i, is64)], 1);
    __syncthreads();
    if (t < C_CLUST && s[t]) atomicAdd(&g_count[t], s[t]);
}

__global__ void k_offsets(int n) {
    if (threadIdx.x == 0) {
        int o = 0, g1 = 0, g2 = 0;
        for (int c = 0; c < C_CLUST; c++) {
            g_off[c] = o; o += g_count[c];
            int mt = (g_count[c] + 127) >> 7;
            g_g1s[c] = g1; g1 += 4 * mt;
            g_g2s[c] = g2; g2 += 4 * mt;
        }
        g_g1s[C_CLUST] = g1;
        g_g2s[C_CLUST] = g2;
        int ng = (n + GROWS - 1) / GROWS;
        g_ng = ng;
        g_tb[0] = ng;                         // end gather
        g_tb[1] = ng + NCONV;                 // end conv
        g_tb[2] = g_tb[1] + g1;               // end G1
        g_tb[3] = g_tb[2] + g2;               // end G2
        g_tb[4] = g_tb[3] + NE1;              // end E1 (fc)
        g_tb[5] = g_tb[4] + NE2;              // end E2 (att)
        g_tb[6] = g_tb[5] + NE3;              // end E3 (rho)
        g_ntask = g_tb[6] + 1;                // + E4
    }
}

// ---------------- gather task ----------------
__device__ void gather_task(const float* __restrict__ x, const void* __restrict__ cid,
                            int n, int base, char* dsm, int tid) {
    int* slot = (int*)dsm;
    if (tid < GROWS) {
        int p = base + tid;
        int s = -1;
        if (p < n) {
            int is64 = detect64(cid);
            int c = get_cid(cid, p, is64);
            s = g_off[c] + atomicAdd(&g_cursor[c], 1);
        }
        slot[tid] = s;
    }
    __syncthreads();
    int r = tid >> 3, q = tid & 7;           // 8 threads per row
    int p = base + r;
    if (p < n) {
        int dst = slot[r];
        const float4* src = (const float4*)(x + (size_t)p * D_IN);
        uint2* d = (uint2*)(g_Xg + (size_t)dst * D_IN);
#pragma unroll 8
        for (int i = 0; i < 32; i++) {
            float4 v = src[i * 8 + q];
            __nv_bfloat162 lo = __floats2bfloat162_rn(v.x, v.y);
            __nv_bfloat162 hi = __floats2bfloat162_rn(v.z, v.w);
            uint2 u;
            u.x = *(uint32_t*)&lo;
            u.y = *(uint32_t*)&hi;
            d[i * 8 + q] = u;
        }
    }
    __threadfence();
    __syncthreads();
    if (tid == 0) atomicAdd(&g_gather_done, 1);
    __syncthreads();
}

// ---------------- conv tile ----------------
__device__ void conv_tile(const float* __restrict__ src, __nv_bfloat16* __restrict__ dst,
                          int R, int C, int r0, int c0, float* sm, int tid) {
    int r = tid >> 1;
    int cb = (tid & 1) * 64;
    const float* s = src + (size_t)(r0 + r) * C + c0 + cb;
#pragma unroll
    for (int q = 0; q < 16; q++) {
        float4 v = *(const float4*)(s + q * 4);
        float* d = sm + r * 129 + cb + q * 4;
        d[0] = v.x; d[1] = v.y; d[2] = v.z; d[3] = v.w;
    }
    __syncthreads();
#pragma unroll
    for (int q = 0; q < 16; q++) {
        int lin = q * 256 + tid;
        int j = lin >> 5;
        int i4 = (lin & 31) * 4;
        float a0 = sm[(i4 + 0) * 129 + j];
        float a1 = sm[(i4 + 1) * 129 + j];
        float a2 = sm[(i4 + 2) * 129 + j];
        float a3 = sm[(i4 + 3) * 129 + j];
        __nv_bfloat162 lo = __floats2bfloat162_rn(a0, a1);
        __nv_bfloat162 hi = __floats2bfloat162_rn(a2, a3);
        uint2 u;
        u.x = *(uint32_t*)&lo;
        u.y = *(uint32_t*)&hi;
        *(uint2*)(dst + (size_t)(c0 + j) * R + r0 + i4) = u;
    }
    __syncthreads();
}

// ---------------- GEMM tile (round-10 validated 2-stage) ----------------
template <bool POOL>
__device__ __forceinline__ void gemm_tile(
    const __nv_bfloat16* __restrict__ Aglob, const __nv_bfloat16* __restrict__ Wc,
    const float* __restrict__ bias_c, float* __restrict__ pool_c,
    int K, int M, int seg, int m0, int n0, char* dsm, float* s_col, int tid) {

    uint32_t sbase = smem_u32(dsm);
    int lane = tid & 31;
    int w = tid >> 5;
    int wm = w & 1;
    int wn = w >> 1;
    int g = lane >> 2;
    int tig = lane & 3;
    int l7 = lane & 7, l8 = (lane >> 3) & 1, l16 = lane >> 4;

    float acc[4][4][4];
#pragma unroll
    for (int im = 0; im < 4; im++)
#pragma unroll
        for (int in = 0; in < 4; in++)
#pragma unroll
            for (int q = 0; q < 4; q++) acc[im][in][q] = 0.f;

    int ar = tid >> 1;
    int acs = (tid & 1) * 4;
    const __nv_bfloat16* Arow = Aglob + (size_t)(seg + m0 + ar) * K + acs * 8;
    const __nv_bfloat16* Brow = Wc + (size_t)(n0 + ar) * K + acs * 8;
    uint32_t a_sm = ar * ROWB + acs * 16;
    uint32_t b_sm = A_BYTES + a_sm;

    uint32_t a_frag = (uint32_t)(wm * 64 + l7 + 8 * l8) * ROWB + 16 * l16;
    uint32_t b_frag = A_BYTES + (uint32_t)(wn * 32 + l7 + 8 * l8) * ROWB + 16 * l16;

    int nch = K / KC;
    {
        uint32_t st = sbase;
#pragma unroll
        for (int q = 0; q < 4; q++) cp16(st + a_sm + q * 16, Arow + q * 8);
#pragma unroll
        for (int q = 0; q < 4; q++) cp16(st + b_sm + q * 16, Brow + q * 8);
        asm volatile("cp.async.commit_group;" ::: "memory");
    }

    for (int c = 0; c < nch; c++) {
        if (c + 1 < nch) {
            uint32_t st = sbase + ((c + 1) & 1) * STAGE_BYTES;
            const __nv_bfloat16* ap = Arow + (c + 1) * KC;
            const __nv_bfloat16* bp = Brow + (c + 1) * KC;
#pragma unroll
            for (int q = 0; q < 4; q++) cp16(st + a_sm + q * 16, ap + q * 8);
#pragma unroll
            for (int q = 0; q < 4; q++) cp16(st + b_sm + q * 16, bp + q * 8);
            asm volatile("cp.async.commit_group;" ::: "memory");
            asm volatile("cp.async.wait_group 1;" ::: "memory");
        } else {
            asm volatile("cp.async.wait_group 0;" ::: "memory");
        }
        __syncthreads();

        uint32_t stb = sbase + (c & 1) * STAGE_BYTES;
#pragma unroll
        for (int ks = 0; ks < 4; ks++) {
            uint32_t koff = ks * 32;
            uint32_t bfr[2][4];
#pragma unroll
            for (int p = 0; p < 2; p++)
                ldsm4(bfr[p][0], bfr[p][1], bfr[p][2], bfr[p][3],
                      stb + b_frag + p * (16 * ROWB) + koff);
            uint32_t afr[4][4];
#pragma unroll
            for (int im = 0; im < 4; im++)
                ldsm4(afr[im][0], afr[im][1], afr[im][2], afr[im][3],
                      stb + a_frag + im * (16 * ROWB) + koff);
#pragma unroll
            for (int im = 0; im < 4; im++) {
#pragma unroll
                for (int p = 0; p < 2; p++) {
                    mma_bf16(acc[im][2 * p],     afr[im][0], afr[im][1], afr[im][2], afr[im][3],
                             bfr[p][0], bfr[p][2]);
                    mma_bf16(acc[im][2 * p + 1], afr[im][0], afr[im][1], afr[im][2], afr[im][3],
                             bfr[p][1], bfr[p][3]);
                }
            }
        }
        __syncthreads();
    }

    const float* bp = bias_c + n0;

    if (!POOL) {
#pragma unroll
        for (int im = 0; im < 4; im++) {
            int rg = m0 + wm * 64 + im * 16 + g;
            int rg8 = rg + 8;
#pragma unroll
            for (int in = 0; in < 4; in++) {
                int col = wn * 32 + in * 8 + 2 * tig;
                float b0v = bp[col], b1v = bp[col + 1];
                if (rg < M) {
                    __nv_bfloat162 v = __floats2bfloat162_rn(
                        fmaxf(acc[im][in][0] + b0v, 0.f), fmaxf(acc[im][in][1] + b1v, 0.f));
                    *(__nv_bfloat162*)&g_H1[(size_t)(seg + rg) * D_H + n0 + col] = v;
                }
                if (rg8 < M) {
                    __nv_bfloat162 v = __floats2bfloat162_rn(
                        fmaxf(acc[im][in][2] + b0v, 0.f), fmaxf(acc[im][in][3] + b1v, 0.f));
                    *(__nv_bfloat162*)&g_H1[(size_t)(seg + rg8) * D_H + n0 + col] = v;
                }
            }
        }
    } else {
        if (tid < 128) s_col[tid] = 0.f;
        __syncthreads();
#pragma unroll
        for (int in = 0; in < 4; in++) {
            int col = wn * 32 + in * 8 + 2 * tig;
            float b0v = bp[col], b1v = bp[col + 1];
            float px = 0.f, py = 0.f;
#pragma unroll
            for (int im = 0; im < 4; im++) {
                int rg = m0 + wm * 64 + im * 16 + g;
                if (rg < M) {
                    px += fmaxf(acc[im][in][0] + b0v, 0.f);
                    py += fmaxf(acc[im][in][1] + b1v, 0.f);
                }
                if (rg + 8 < M) {
                    px += fmaxf(acc[im][in][2] + b0v, 0.f);
                    py += fmaxf(acc[im][in][3] + b1v, 0.f);
                }
            }
            atomicAdd(&s_col[col], px);
            atomicAdd(&s_col[col + 1], py);
        }
        __syncthreads();
        if (tid < 128) atomicAdd(&pool_c[n0 + tid], s_col[tid]);
    }
}

// ---------------- E1: fc, one 32-col block for all clusters ----------------
__device__ void e1_task(int i, const float* __restrict__ Wfc, const float* __restrict__ bfc,
                        char* dsm, int tid) {
    float* ph = (float*)dsm;          // 512
    float* s_p = ph + D_H;            // 256
    int j0 = i * 32;
    int j = tid & 31, ks = tid >> 5;
    for (int c = 0; c < C_CLUST; c++) {
        float inv = 1.f / (float)max(g_count[c], 1);
        for (int q = tid; q < D_H; q += 256) ph[q] = g_pool[c * D_H + q] * inv;
        __syncthreads();
        float p = 0.f;
#pragma unroll 8
        for (int k = ks * 64; k < ks * 64 + 64; k++)
            p += ph[k] * Wfc[k * D_H + j0 + j];
        s_p[ks * 32 + j] = p;
        __syncthreads();
        if (tid < 32) {
            float s = 0.f;
#pragma unroll
            for (int q = 0; q < 8; q++) s += s_p[q * 32 + tid];
            g_hbuf[c * D_H + j0 + tid] = fmaxf(s + bfc[j0 + tid], 0.f);
        }
        __syncthreads();
    }
    __threadfence();
    __syncthreads();
    if (tid == 0) atomicAdd(&g_e1, 1);
    __syncthreads();
}

// ---------------- E2: gated attention, one 32-col block for all clusters ----------------
__device__ void e2_task(int i, const float* __restrict__ Wa, const float* __restrict__ ba,
                        const float* __restrict__ Wb, const float* __restrict__ bb,
                        const float* __restrict__ Wcs, char* dsm, int tid) {
    float* h = (float*)dsm;           // 5120
    float* s_sa = h + C_CLUST * D_H;  // 256
    float* s_sb = s_sa + 256;         // 256
    int col0 = i * 32;
    int col = tid & 31, ks = tid >> 5;
    for (int q = tid; q < C_CLUST * D_H; q += 256) h[q] = g_hbuf[q];
    __syncthreads();
    for (int c = 0; c < C_CLUST; c++) {
        const float* hc = h + c * D_H;
        float sa = 0.f, sb = 0.f;
#pragma unroll 8
        for (int k = ks * 64; k < ks * 64 + 64; k++) {
            float hv = hc[k];
            sa += hv * Wa[k * D_ATT + col0 + col];
            sb += hv * Wb[k * D_ATT + col0 + col];
        }
        s_sa[ks * 32 + col] = sa;
        s_sb[ks * 32 + col] = sb;
        __syncthreads();
        if (tid < 32) {
            float ta = 0.f, tb = 0.f;
#pragma unroll
            for (int q = 0; q < 8; q++) { ta += s_sa[q * 32 + tid]; tb += s_sb[q * 32 + tid]; }
            float gate = tanhf(ta + ba[col0 + tid]) *
                         (1.f / (1.f + expf(-(tb + bb[col0 + tid]))));
            float part = gate * Wcs[col0 + tid];
#pragma unroll
            for (int off = 16; off > 0; off >>= 1)
                part += __shfl_down_sync(0xffffffff, part, off);
            if (tid == 0) atomicAdd(&g_AccA[c], part);
        }
        __syncthreads();
    }
    __threadfence();
    __syncthreads();
    if (tid == 0) atomicAdd(&g_e2, 1);
    __syncthreads();
}

// ---------------- E3: softmax + h_path + rho (32-col block) ----------------
__device__ void e3_task(int i, const float* __restrict__ bcs,
                        const float* __restrict__ Wr, const float* __restrict__ br,
                        char* dsm, int tid) {
    float* A = (float*)dsm;           // 16
    float* hp = A + 16;               // 512
    float* s_p = hp + D_H;            // 256
    int j0 = i * 32;
    if (tid == 0) {
        float m = -1e30f;
        float araw[C_CLUST];
        for (int c = 0; c < C_CLUST; c++) { araw[c] = g_AccA[c] + bcs[0]; m = fmaxf(m, araw[c]); }
        float s = 0.f;
        for (int c = 0; c < C_CLUST; c++) { A[c] = expf(araw[c] - m); s += A[c]; }
        float inv = 1.f / s;
        for (int c = 0; c < C_CLUST; c++) A[c] *= inv;
    }
    __syncthreads();
    for (int k = tid; k < D_H; k += 256) {
        float s = 0.f;
#pragma unroll
        for (int c = 0; c < C_CLUST; c++) s += A[c] * g_hbuf[c * D_H + k];
        hp[k] = s;
    }
    __syncthreads();
    int j = tid & 31, ks = tid >> 5;
    float p = 0.f;
#pragma unroll 8
    for (int k = ks * 64; k < ks * 64 + 64; k++)
        p += hp[k] * Wr[k * D_ATT + j0 + j];
    s_p[ks * 32 + j] = p;
    __syncthreads();
    if (tid < 32) {
        float s = 0.f;
#pragma unroll
        for (int q = 0; q < 8; q++) s += s_p[q * 32 + tid];
        g_hr[j0 + tid] = fmaxf(s + br[j0 + tid], 0.f);
    }
    __threadfence();
    __syncthreads();
    if (tid == 0) atomicAdd(&g_e3, 1);
    __syncthreads();
}

// ---------------- E4: classifier + softmax + argmax + output ----------------
__device__ void e4_task(const float* __restrict__ Wcls, const float* __restrict__ bcls,
                        float* __restrict__ out, int out_size, char* dsm, int tid) {
    float* hr = (float*)dsm;          // 256
    float* red = hr + 256;            // 256
    float* lg = red + 256;            // 4
    hr[tid] = g_hr[tid];
    __syncthreads();
    for (int i = 0; i < N_CLS; i++) {
        red[tid] = hr[tid] * Wcls[tid * N_CLS + i];
        __syncthreads();
        for (int s = 128; s > 0; s >>= 1) {
            if (tid < s) red[tid] += red[tid + s];
            __syncthreads();
        }
        if (tid == 0) lg[i] = red[0] + bcls[i];
        __syncthreads();
    }
    if (tid == 0) {
        float m = lg[0];
        int am = 0;
        for (int i = 1; i < N_CLS; i++) if (lg[i] > m) { m = lg[i]; am = i; }
        float e[N_CLS], s = 0.f;
        for (int i = 0; i < N_CLS; i++) { e[i] = expf(lg[i] - m); s += e[i]; }
        float vals[9];
        for (int i = 0; i < N_CLS; i++) vals[i] = lg[i];
        for (int i = 0; i < N_CLS; i++) vals[4 + i] = e[i] / s;
        vals[8] = (float)am;
        for (int i = 0; i < out_size; i++) out[i] = (i < 9) ? vals[i] : 0.f;
    }
    __syncthreads();
}

// ---------------- persistent mega kernel ----------------
__global__ void __launch_bounds__(256, 2)
k_mega(const float* __restrict__ x, const void* __restrict__ cid, int n,
       const float* __restrict__ W1, const float* __restrict__ W2,
       const float* __restrict__ b1, const float* __restrict__ b2,
       const float* __restrict__ Wfc, const float* __restrict__ bfc,
       const float* __restrict__ Wa, const float* __restrict__ ba,
       const float* __restrict__ Wb, const float* __restrict__ bb,
       const float* __restrict__ Wcs, const float* __restrict__ bcs,
       const float* __restrict__ Wr, const float* __restrict__ br,
       const float* __restrict__ Wcls, const float* __restrict__ bcls,
       float* __restrict__ out, int out_size) {
    extern __shared__ char dsm[];
    __shared__ float s_col[128];
    __shared__ int s_task;
    int tid = threadIdx.x;

    int ng = g_ng;
    int tb0 = g_tb[0], tb1 = g_tb[1], tb2 = g_tb[2], tb3 = g_tb[3];
    int tb4 = g_tb[4], tb5 = g_tb[5], tb6 = g_tb[6];
    int ntask = g_ntask;
    int g2_total = g_g2s[C_CLUST];

    for (;;) {
        if (tid == 0) s_task = atomicAdd(&g_task, 1);
        __syncthreads();
        int t = s_task;
        if (t >= ntask) break;

        if (t < tb0) {
            gather_task(x, cid, n, t * GROWS, dsm, tid);
        } else if (t < tb1) {
            int tc = t - tb0;
            if (tc < NCONV_W1) {
                int c = tc >> 5, rem = tc & 31;
                conv_tile(W1 + (size_t)c * D_IN * D_H, g_W1t + (size_t)c * D_H * D_IN,
                          D_IN, D_H, (rem >> 2) * 128, (rem & 3) * 128, (float*)dsm, tid);
            } else {
                int t2 = tc - NCONV_W1;
                int c = t2 >> 4, rem = t2 & 15;
                conv_tile(W2 + (size_t)c * D_H * D_H, g_W2t + (size_t)c * D_H * D_H,
                          D_H, D_H, (rem >> 2) * 128, (rem & 3) * 128, (float*)dsm, tid);
            }
            __threadfence();
            __syncthreads();
            if (tid == 0) atomicAdd(&g_conv_done, 1);
        } else if (t < tb2) {
            int t1 = t - tb1;
            int c = 0;
#pragma unroll
            for (int cc = 0; cc < C_CLUST; cc++) if (t1 >= g_g1s[cc + 1]) c = cc + 1;
            int rem = t1 - g_g1s[c];
            int m0 = (rem >> 2) * 128, n0 = (rem & 3) * 128;
            if (tid == 0) {
                SPIN_WAIT(ldacq(&g_gather_done) < ng || ldacq(&g_conv_done) < NCONV);
            }
            __syncthreads();
            gemm_tile<false>(g_Xg, g_W1t + (size_t)c * D_H * D_IN, b1 + c * D_H, nullptr,
                             D_IN, g_count[c], g_off[c], m0, n0, dsm, s_col, tid);
            __threadfence();
            __syncthreads();
            if (tid == 0) atomicAdd(&g_g1_done[c], 1);
        } else if (t < tb3) {
            int t2 = t - tb2;
            int c = 0;
#pragma unroll
            for (int cc = 0; cc < C_CLUST; cc++) if (t2 >= g_g2s[cc + 1]) c = cc + 1;
            int rem = t2 - g_g2s[c];
            int m0 = (rem >> 2) * 128, n0 = (rem & 3) * 128;
            int target = g_g2s[c + 1] - g_g2s[c];
            if (tid == 0) { SPIN_WAIT(ldacq(&g_g1_done[c]) < target); }
            __syncthreads();
            gemm_tile<true>(g_H1, g_W2t + (size_t)c * D_H * D_H, b2 + c * D_H,
                            g_pool + c * D_H, D_H, g_count[c], g_off[c], m0, n0, dsm, s_col, tid);
            __threadfence();
            __syncthreads();
            if (tid == 0) atomicAdd(&g_g2_all, 1);
        } else if (t < tb4) {
            if (tid == 0) { SPIN_WAIT(ldacq(&g_g2_all) < g2_total); }
            __syncthreads();
            e1_task(t - tb3, Wfc, bfc, dsm, tid);
        } else if (t < tb5) {
            if (tid == 0) { SPIN_WAIT(ldacq(&g_e1) < NE1); }
            __syncthreads();
            e2_task(t - tb4, Wa, ba, Wb, bb, Wcs, dsm, tid);
        } else if (t < tb6) {
            if (tid == 0) { SPIN_WAIT(ldacq(&g_e2) < NE2); }
            __syncthreads();
            e3_task(t - tb5, bcs, Wr, br, dsm, tid);
        } else {
            if (tid == 0) { SPIN_WAIT(ldacq(&g_e3) < NE3); }
            __syncthreads();
            e4_task(Wcls, bcls, out, out_size, dsm, tid);
        }
        __syncthreads();
    }
}

// ---------------- launch ----------------
extern "C" void kernel_launch(void* const* d_in, const int* in_sizes, int n_in,
                              void* d_out, int out_size) {
    const float* x    = (const float*)d_in[0];
    const void*  cid  = d_in[1];
    const float* W1   = (const float*)d_in[2];
    const float* b1   = (const float*)d_in[3];
    const float* W2   = (const float*)d_in[4];
    const float* b2   = (const float*)d_in[5];
    const float* Wfc  = (const float*)d_in[6];
    const float* bfc  = (const float*)d_in[7];
    const float* Wa   = (const float*)d_in[8];
    const float* ba   = (const float*)d_in[9];
    const float* Wb   = (const float*)d_in[10];
    const float* bb   = (const float*)d_in[11];
    const float* Wc_  = (const float*)d_in[12];
    const float* bc_  = (const float*)d_in[13];
    const float* Wr   = (const float*)d_in[14];
    const float* br   = (const float*)d_in[15];
    const float* Wcls = (const float*)d_in[16];
    const float* bcls = (const float*)d_in[17];

    int n = in_sizes[0] / D_IN;

    static int nsm = 0;
    if (!nsm) {
        cudaDeviceProp prop;
        cudaGetDeviceProperties(&prop, 0);
        nsm = prop.multiProcessorCount;
        cudaFuncSetAttribute(k_mega, cudaFuncAttributeMaxDynamicSharedMemorySize, SMEM_SZ);
    }

    k_reset<<<1, 512>>>();                                     // 1
    k_count<<<(n + 255) / 256, 256>>>(cid, n);                 // 2
    k_offsets<<<1, 32>>>(n);                                   // 3
    k_mega<<<2 * nsm, 256, SMEM_SZ>>>(                         // 4  <- ncu target
        x, cid, n, W1, W2, b1, b2, Wfc, bfc, Wa, ba, Wb, bb,
        Wc_, bc_, Wr, br, Wcls, bcls, (float*)d_out, out_size);
}

// round 14
// speedup vs baseline: 1.6441x; 1.2555x over previous
#include <cuda_runtime.h>
#include <cuda_bf16.h>
#include <math.h>
#include <stdint.h>

#define C_CLUST 10
#define D_IN    1024
#define D_H     512
#define D_ATT   256
#define N_CLS   4
#define N_MAX   10000
#define NPAD    128

#define KC 64
#define ROWB 144                            // smem row stride bytes (72 bf16)
#define A_BYTES (128 * ROWB)                // 18432
#define STAGE_BYTES (2 * A_BYTES)           // 36864
#define SMEM_SZ (2 * STAGE_BYTES)           // 73728

#define NCONV_W1 320                        // 10 * (1024/128)*(512/128)
#define NCONV_W2 160                        // 10 * (512/128)*(512/128)
#define GROWS    32
#define NE1T     160                        // E1: (cluster, 32-col block)
#define NE2T     80                         // E2: (cluster, 32-attcol block)
#define NE3      8                          // E3: 32-col blocks of rho

// ---------------- scratch ----------------
__device__ int   g_count[C_CLUST];
__device__ int   g_off[C_CLUST];
__device__ int   g_cursor[C_CLUST];
__device__ int   g_g1s[C_CLUST + 1];
__device__ int   g_g2s[C_CLUST + 1];
__device__ int   g_ng;
__device__ int   g_tb[8];                   // task boundaries
__device__ int   g_ntask;
__device__ int   g_task;
__device__ int   g_gather_done;
__device__ int   g_cw1, g_cw2;
__device__ int   g_g1_done[C_CLUST];
__device__ int   g_g2_done[C_CLUST];
__device__ int   g_e1c[C_CLUST];
__device__ int   g_e2, g_e3;
__device__ __nv_bfloat16 g_Xg[(size_t)(N_MAX + NPAD) * D_IN];
__device__ __nv_bfloat16 g_H1[(size_t)(N_MAX + NPAD) * D_H];
__device__ __nv_bfloat16 g_W1t[(size_t)C_CLUST * D_H * D_IN];
__device__ __nv_bfloat16 g_W2t[(size_t)C_CLUST * D_H * D_H];
__device__ float g_pool[C_CLUST * D_H];
__device__ float g_hbuf[C_CLUST * D_H];
__device__ float g_AccA[C_CLUST];
__device__ float g_hr[D_ATT];

__device__ __forceinline__ int detect64(const void* cid) {
    const int* p = (const int*)cid;
    int allz = 1;
#pragma unroll
    for (int i = 1; i < 32; i += 2) if (p[i] != 0) allz = 0;
    return allz;
}
__device__ __forceinline__ int get_cid(const void* cid, int n, int is64) {
    if (is64) return (int)((const long long*)cid)[n];
    return ((const int*)cid)[n];
}
__device__ __forceinline__ uint32_t smem_u32(const void* p) {
    uint32_t a;
    asm("{ .reg .u64 t; cvta.to.shared.u64 t, %1; cvt.u32.u64 %0, t; }" : "=r"(a) : "l"(p));
    return a;
}
__device__ __forceinline__ void cp16(uint32_t smem, const void* gmem) {
    asm volatile("cp.async.cg.shared.global [%0], [%1], 16;" :: "r"(smem), "l"(gmem));
}
__device__ __forceinline__ void ldsm4(uint32_t& r0, uint32_t& r1, uint32_t& r2, uint32_t& r3,
                                      uint32_t addr) {
    asm volatile("ldmatrix.sync.aligned.m8n8.x4.shared.b16 {%0,%1,%2,%3}, [%4];"
                 : "=r"(r0), "=r"(r1), "=r"(r2), "=r"(r3) : "r"(addr));
}
__device__ __forceinline__ void mma_bf16(float c[4], uint32_t a0, uint32_t a1, uint32_t a2,
                                         uint32_t a3, uint32_t b0, uint32_t b1) {
    asm volatile(
        "mma.sync.aligned.m16n8k16.row.col.f32.bf16.bf16.f32 "
        "{%0,%1,%2,%3}, {%4,%5,%6,%7}, {%8,%9}, {%0,%1,%2,%3};\n"
        : "+f"(c[0]), "+f"(c[1]), "+f"(c[2]), "+f"(c[3])
        : "r"(a0), "r"(a1), "r"(a2), "r"(a3), "r"(b0), "r"(b1));
}
__device__ __forceinline__ int ldacq(const int* p) {
    int v; asm volatile("ld.acquire.gpu.s32 %0, [%1];" : "=r"(v) : "l"(p)); return v;
}
#define SPIN_WAIT(cond) do {                      \
    int _sl = 64;                                 \
    while (cond) {                                \
        __nanosleep(_sl);                         \
        if (_sl < 2048) _sl <<= 1;                \
    }                                             \
} while (0)

// ---------------- prep kernels ----------------
__global__ void k_reset() {
    int t = threadIdx.x;   // 512
    for (int i = t; i < C_CLUST * D_H; i += 512) g_pool[i] = 0.f;
    if (t < C_CLUST) {
        g_count[t] = 0; g_cursor[t] = 0; g_g1_done[t] = 0; g_g2_done[t] = 0;
        g_e1c[t] = 0; g_AccA[t] = 0.f;
    }
    if (t == 0) {
        g_task = 0; g_gather_done = 0; g_cw1 = 0; g_cw2 = 0; g_e2 = 0; g_e3 = 0;
    }
}

__global__ void k_count(const void* __restrict__ cid, int n) {
    __shared__ int s[C_CLUST];
    int t = threadIdx.x;
    int is64 = detect64(cid);
    if (t < C_CLUST) s[t] = 0;
    __syncthreads();
    int i = blockIdx.x * blockDim.x + t;
    if (i < n) atomicAdd(&s[get_cid(cid, i, is64)], 1);
    __syncthreads();
    if (t < C_CLUST && s[t]) atomicAdd(&g_count[t], s[t]);
}

__global__ void k_offsets(int n) {
    if (threadIdx.x == 0) {
        int o = 0, g1 = 0, g2 = 0;
        for (int c = 0; c < C_CLUST; c++) {
            g_off[c] = o; o += g_count[c];
            int mt = (g_count[c] + 127) >> 7;
            g_g1s[c] = g1; g1 += 4 * mt;
            g_g2s[c] = g2; g2 += 4 * mt;
        }
        g_g1s[C_CLUST] = g1;
        g_g2s[C_CLUST] = g2;
        int ng = (n + GROWS - 1) / GROWS;
        g_ng = ng;
        g_tb[0] = ng;                         // end gather
        g_tb[1] = g_tb[0] + NCONV_W1;         // end conv W1
        g_tb[2] = g_tb[1] + g1;               // end G1
        g_tb[3] = g_tb[2] + NCONV_W2;         // end conv W2
        g_tb[4] = g_tb[3] + g2;               // end G2
        g_tb[5] = g_tb[4] + NE1T;             // end E1
        g_tb[6] = g_tb[5] + NE2T;             // end E2
        g_tb[7] = g_tb[6] + NE3;              // end E3
        g_ntask = g_tb[7] + 1;                // + E4
    }
}

// ---------------- gather task ----------------
__device__ void gather_task(const float* __restrict__ x, const void* __restrict__ cid,
                            int n, int base, char* dsm, int tid) {
    int* slot = (int*)dsm;
    if (tid < GROWS) {
        int p = base + tid;
        int s = -1;
        if (p < n) {
            int is64 = detect64(cid);
            int c = get_cid(cid, p, is64);
            s = g_off[c] + atomicAdd(&g_cursor[c], 1);
        }
        slot[tid] = s;
    }
    __syncthreads();
    int r = tid >> 3, q = tid & 7;           // 8 threads per row
    int p = base + r;
    if (p < n) {
        int dst = slot[r];
        const float4* src = (const float4*)(x + (size_t)p * D_IN);
        uint2* d = (uint2*)(g_Xg + (size_t)dst * D_IN);
#pragma unroll 8
        for (int i = 0; i < 32; i++) {
            float4 v = src[i * 8 + q];
            __nv_bfloat162 lo = __floats2bfloat162_rn(v.x, v.y);
            __nv_bfloat162 hi = __floats2bfloat162_rn(v.z, v.w);
            uint2 u;
            u.x = *(uint32_t*)&lo;
            u.y = *(uint32_t*)&hi;
            d[i * 8 + q] = u;
        }
    }
    __threadfence();
    __syncthreads();
    if (tid == 0) atomicAdd(&g_gather_done, 1);
    __syncthreads();
}

// ---------------- conv tile: 128x128 transpose fp32 -> bf16 ----------------
__device__ void conv_tile(const float* __restrict__ src, __nv_bfloat16* __restrict__ dst,
                          int R, int C, int r0, int c0, float* sm, int tid) {
    int r = tid >> 1;
    int cb = (tid & 1) * 64;
    const float* s = src + (size_t)(r0 + r) * C + c0 + cb;
#pragma unroll
    for (int q = 0; q < 16; q++) {
        float4 v = *(const float4*)(s + q * 4);
        float* d = sm + r * 129 + cb + q * 4;
        d[0] = v.x; d[1] = v.y; d[2] = v.z; d[3] = v.w;
    }
    __syncthreads();
#pragma unroll
    for (int q = 0; q < 16; q++) {
        int lin = q * 256 + tid;
        int j = lin >> 5;
        int i4 = (lin & 31) * 4;
        float a0 = sm[(i4 + 0) * 129 + j];
        float a1 = sm[(i4 + 1) * 129 + j];
        float a2 = sm[(i4 + 2) * 129 + j];
        float a3 = sm[(i4 + 3) * 129 + j];
        __nv_bfloat162 lo = __floats2bfloat162_rn(a0, a1);
        __nv_bfloat162 hi = __floats2bfloat162_rn(a2, a3);
        uint2 u;
        u.x = *(uint32_t*)&lo;
        u.y = *(uint32_t*)&hi;
        *(uint2*)(dst + (size_t)(c0 + j) * R + r0 + i4) = u;
    }
    __syncthreads();
}

// ---------------- GEMM tile (round-10 validated 2-stage) ----------------
template <bool POOL>
__device__ __forceinline__ void gemm_tile(
    const __nv_bfloat16* __restrict__ Aglob, const __nv_bfloat16* __restrict__ Wc,
    const float* __restrict__ bias_c, float* __restrict__ pool_c,
    int K, int M, int seg, int m0, int n0, char* dsm, float* s_col, int tid) {

    uint32_t sbase = smem_u32(dsm);
    int lane = tid & 31;
    int w = tid >> 5;
    int wm = w & 1;
    int wn = w >> 1;
    int g = lane >> 2;
    int tig = lane & 3;
    int l7 = lane & 7, l8 = (lane >> 3) & 1, l16 = lane >> 4;

    float acc[4][4][4];
#pragma unroll
    for (int im = 0; im < 4; im++)
#pragma unroll
        for (int in = 0; in < 4; in++)
#pragma unroll
            for (int q = 0; q < 4; q++) acc[im][in][q] = 0.f;

    int ar = tid >> 1;
    int acs = (tid & 1) * 4;
    const __nv_bfloat16* Arow = Aglob + (size_t)(seg + m0 + ar) * K + acs * 8;
    const __nv_bfloat16* Brow = Wc + (size_t)(n0 + ar) * K + acs * 8;
    uint32_t a_sm = ar * ROWB + acs * 16;
    uint32_t b_sm = A_BYTES + a_sm;

    uint32_t a_frag = (uint32_t)(wm * 64 + l7 + 8 * l8) * ROWB + 16 * l16;
    uint32_t b_frag = A_BYTES + (uint32_t)(wn * 32 + l7 + 8 * l8) * ROWB + 16 * l16;

    int nch = K / KC;
    {
        uint32_t st = sbase;
#pragma unroll
        for (int q = 0; q < 4; q++) cp16(st + a_sm + q * 16, Arow + q * 8);
#pragma unroll
        for (int q = 0; q < 4; q++) cp16(st + b_sm + q * 16, Brow + q * 8);
        asm volatile("cp.async.commit_group;" ::: "memory");
    }

    for (int c = 0; c < nch; c++) {
        if (c + 1 < nch) {
            uint32_t st = sbase + ((c + 1) & 1) * STAGE_BYTES;
            const __nv_bfloat16* ap = Arow + (c + 1) * KC;
            const __nv_bfloat16* bp = Brow + (c + 1) * KC;
#pragma unroll
            for (int q = 0; q < 4; q++) cp16(st + a_sm + q * 16, ap + q * 8);
#pragma unroll
            for (int q = 0; q < 4; q++) cp16(st + b_sm + q * 16, bp + q * 8);
            asm volatile("cp.async.commit_group;" ::: "memory");
            asm volatile("cp.async.wait_group 1;" ::: "memory");
        } else {
            asm volatile("cp.async.wait_group 0;" ::: "memory");
        }
        __syncthreads();

        uint32_t stb = sbase + (c & 1) * STAGE_BYTES;
#pragma unroll
        for (int ks = 0; ks < 4; ks++) {
            uint32_t koff = ks * 32;
            uint32_t bfr[2][4];
#pragma unroll
            for (int p = 0; p < 2; p++)
                ldsm4(bfr[p][0], bfr[p][1], bfr[p][2], bfr[p][3],
                      stb + b_frag + p * (16 * ROWB) + koff);
            uint32_t afr[4][4];
#pragma unroll
            for (int im = 0; im < 4; im++)
                ldsm4(afr[im][0], afr[im][1], afr[im][2], afr[im][3],
                      stb + a_frag + im * (16 * ROWB) + koff);
#pragma unroll
            for (int im = 0; im < 4; im++) {
#pragma unroll
                for (int p = 0; p < 2; p++) {
                    mma_bf16(acc[im][2 * p],     afr[im][0], afr[im][1], afr[im][2], afr[im][3],
                             bfr[p][0], bfr[p][2]);
                    mma_bf16(acc[im][2 * p + 1], afr[im][0], afr[im][1], afr[im][2], afr[im][3],
                             bfr[p][1], bfr[p][3]);
                }
            }
        }
        __syncthreads();
    }

    const float* bp = bias_c + n0;

    if (!POOL) {
#pragma unroll
        for (int im = 0; im < 4; im++) {
            int rg = m0 + wm * 64 + im * 16 + g;
            int rg8 = rg + 8;
#pragma unroll
            for (int in = 0; in < 4; in++) {
                int col = wn * 32 + in * 8 + 2 * tig;
                float b0v = bp[col], b1v = bp[col + 1];
                if (rg < M) {
                    __nv_bfloat162 v = __floats2bfloat162_rn(
                        fmaxf(acc[im][in][0] + b0v, 0.f), fmaxf(acc[im][in][1] + b1v, 0.f));
                    *(__nv_bfloat162*)&g_H1[(size_t)(seg + rg) * D_H + n0 + col] = v;
                }
                if (rg8 < M) {
                    __nv_bfloat162 v = __floats2bfloat162_rn(
                        fmaxf(acc[im][in][2] + b0v, 0.f), fmaxf(acc[im][in][3] + b1v, 0.f));
                    *(__nv_bfloat162*)&g_H1[(size_t)(seg + rg8) * D_H + n0 + col] = v;
                }
            }
        }
    } else {
        if (tid < 128) s_col[tid] = 0.f;
        __syncthreads();
#pragma unroll
        for (int in = 0; in < 4; in++) {
            int col = wn * 32 + in * 8 + 2 * tig;
            float b0v = bp[col], b1v = bp[col + 1];
            float px = 0.f, py = 0.f;
#pragma unroll
            for (int im = 0; im < 4; im++) {
                int rg = m0 + wm * 64 + im * 16 + g;
                if (rg < M) {
                    px += fmaxf(acc[im][in][0] + b0v, 0.f);
                    py += fmaxf(acc[im][in][1] + b1v, 0.f);
                }
                if (rg + 8 < M) {
                    px += fmaxf(acc[im][in][2] + b0v, 0.f);
                    py += fmaxf(acc[im][in][3] + b1v, 0.f);
                }
            }
            atomicAdd(&s_col[col], px);
            atomicAdd(&s_col[col + 1], py);
        }
        __syncthreads();
        if (tid < 128) atomicAdd(&pool_c[n0 + tid], s_col[tid]);
    }
}

// ---------------- E1: fc, one (cluster, 32-col) task ----------------
__device__ void e1_task(int c, int i, const float* __restrict__ Wfc,
                        const float* __restrict__ bfc, char* dsm, int tid) {
    float* ph = (float*)dsm;          // 512
    float* s_p = ph + D_H;            // 256
    int j0 = i * 32;
    int j = tid & 31, ks = tid >> 5;
    float inv = 1.f / (float)max(g_count[c], 1);
    for (int q = tid; q < D_H; q += 256) ph[q] = g_pool[c * D_H + q] * inv;
    __syncthreads();
    float p = 0.f;
#pragma unroll 8
    for (int k = ks * 64; k < ks * 64 + 64; k++)
        p += ph[k] * Wfc[k * D_H + j0 + j];
    s_p[ks * 32 + j] = p;
    __syncthreads();
    if (tid < 32) {
        float s = 0.f;
#pragma unroll
        for (int q = 0; q < 8; q++) s += s_p[q * 32 + tid];
        g_hbuf[c * D_H + j0 + tid] = fmaxf(s + bfc[j0 + tid], 0.f);
    }
    __threadfence();
    __syncthreads();
    if (tid == 0) atomicAdd(&g_e1c[c], 1);
    __syncthreads();
}

// ---------------- E2: gated attention, one (cluster, 32-attcol) task ----------------
__device__ void e2_task(int c, int i, const float* __restrict__ Wa, const float* __restrict__ ba,
                        const float* __restrict__ Wb, const float* __restrict__ bb,
                        const float* __restrict__ Wcs, char* dsm, int tid) {
    float* hc = (float*)dsm;          // 512
    float* s_sa = hc + D_H;           // 256
    float* s_sb = s_sa + 256;         // 256
    int col0 = i * 32;
    int col = tid & 31, ks = tid >> 5;
    for (int q = tid; q < D_H; q += 256) hc[q] = g_hbuf[c * D_H + q];
    __syncthreads();
    float sa = 0.f, sb = 0.f;
#pragma unroll 8
    for (int k = ks * 64; k < ks * 64 + 64; k++) {
        float hv = hc[k];
        sa += hv * Wa[k * D_ATT + col0 + col];
        sb += hv * Wb[k * D_ATT + col0 + col];
    }
    s_sa[ks * 32 + col] = sa;
    s_sb[ks * 32 + col] = sb;
    __syncthreads();
    if (tid < 32) {
        float ta = 0.f, tb = 0.f;
#pragma unroll
        for (int q = 0; q < 8; q++) { ta += s_sa[q * 32 + tid]; tb += s_sb[q * 32 + tid]; }
        float gate = tanhf(ta + ba[col0 + tid]) *
                     (1.f / (1.f + expf(-(tb + bb[col0 + tid]))));
        float part = gate * Wcs[col0 + tid];
#pragma unroll
        for (int off = 16; off > 0; off >>= 1)
            part += __shfl_down_sync(0xffffffff, part, off);
        if (tid == 0) atomicAdd(&g_AccA[c], part);
    }
    __threadfence();
    __syncthreads();
    if (tid == 0) atomicAdd(&g_e2, 1);
    __syncthreads();
}

// ---------------- E3: softmax + h_path + rho (32-col block) ----------------
__device__ void e3_task(int i, const float* __restrict__ bcs,
                        const float* __restrict__ Wr, const float* __restrict__ br,
                        char* dsm, int tid) {
    float* A = (float*)dsm;           // 16
    float* hp = A + 16;               // 512
    float* s_p = hp + D_H;            // 256
    int j0 = i * 32;
    if (tid == 0) {
        float m = -1e30f;
        float araw[C_CLUST];
        for (int c = 0; c < C_CLUST; c++) { araw[c] = g_AccA[c] + bcs[0]; m = fmaxf(m, araw[c]); }
        float s = 0.f;
        for (int c = 0; c < C_CLUST; c++) { A[c] = expf(araw[c] - m); s += A[c]; }
        float inv = 1.f / s;
        for (int c = 0; c < C_CLUST; c++) A[c] *= inv;
    }
    __syncthreads();
    for (int k = tid; k < D_H; k += 256) {
        float s = 0.f;
#pragma unroll
        for (int c = 0; c < C_CLUST; c++) s += A[c] * g_hbuf[c * D_H + k];
        hp[k] = s;
    }
    __syncthreads();
    int j = tid & 31, ks = tid >> 5;
    float p = 0.f;
#pragma unroll 8
    for (int k = ks * 64; k < ks * 64 + 64; k++)
        p += hp[k] * Wr[k * D_ATT + j0 + j];
    s_p[ks * 32 + j] = p;
    __syncthreads();
    if (tid < 32) {
        float s = 0.f;
#pragma unroll
        for (int q = 0; q < 8; q++) s += s_p[q * 32 + tid];
        g_hr[j0 + tid] = fmaxf(s + br[j0 + tid], 0.f);
    }
    __threadfence();
    __syncthreads();
    if (tid == 0) atomicAdd(&g_e3, 1);
    __syncthreads();
}

// ---------------- E4: classifier + softmax + argmax + output ----------------
__device__ void e4_task(const float* __restrict__ Wcls, const float* __restrict__ bcls,
                        float* __restrict__ out, int out_size, char* dsm, int tid) {
    float* hr = (float*)dsm;          // 256
    float* red = hr + 256;            // 256
    float* lg = red + 256;            // 4
    hr[tid] = g_hr[tid];
    __syncthreads();
    for (int i = 0; i < N_CLS; i++) {
        red[tid] = hr[tid] * Wcls[tid * N_CLS + i];
        __syncthreads();
        for (int s = 128; s > 0; s >>= 1) {
            if (tid < s) red[tid] += red[tid + s];
            __syncthreads();
        }
        if (tid == 0) lg[i] = red[0] + bcls[i];
        __syncthreads();
    }
    if (tid == 0) {
        float m = lg[0];
        int am = 0;
        for (int i = 1; i < N_CLS; i++) if (lg[i] > m) { m = lg[i]; am = i; }
        float e[N_CLS], s = 0.f;
        for (int i = 0; i < N_CLS; i++) { e[i] = expf(lg[i] - m); s += e[i]; }
        float vals[9];
        for (int i = 0; i < N_CLS; i++) vals[i] = lg[i];
        for (int i = 0; i < N_CLS; i++) vals[4 + i] = e[i] / s;
        vals[8] = (float)am;
        for (int i = 0; i < out_size; i++) out[i] = (i < 9) ? vals[i] : 0.f;
    }
    __syncthreads();
}

// ---------------- persistent mega kernel ----------------
__global__ void __launch_bounds__(256, 2)
k_mega(const float* __restrict__ x, const void* __restrict__ cid, int n,
       const float* __restrict__ W1, const float* __restrict__ W2,
       const float* __restrict__ b1, const float* __restrict__ b2,
       const float* __restrict__ Wfc, const float* __restrict__ bfc,
       const float* __restrict__ Wa, const float* __restrict__ ba,
       const float* __restrict__ Wb, const float* __restrict__ bb,
       const float* __restrict__ Wcs, const float* __restrict__ bcs,
       const float* __restrict__ Wr, const float* __restrict__ br,
       const float* __restrict__ Wcls, const float* __restrict__ bcls,
       float* __restrict__ out, int out_size) {
    extern __shared__ char dsm[];
    __shared__ float s_col[128];
    __shared__ int s_task;
    int tid = threadIdx.x;

    int ng = g_ng;
    int tb0 = g_tb[0], tb1 = g_tb[1], tb2 = g_tb[2], tb3 = g_tb[3];
    int tb4 = g_tb[4], tb5 = g_tb[5], tb6 = g_tb[6], tb7 = g_tb[7];
    int ntask = g_ntask;

    for (;;) {
        if (tid == 0) s_task = atomicAdd(&g_task, 1);
        __syncthreads();
        int t = s_task;
        if (t >= ntask) break;

        if (t < tb0) {
            gather_task(x, cid, n, t * GROWS, dsm, tid);
        } else if (t < tb1) {                          // conv W1
            int tc = t - tb0;
            int c = tc >> 5, rem = tc & 31;
            conv_tile(W1 + (size_t)c * D_IN * D_H, g_W1t + (size_t)c * D_H * D_IN,
                      D_IN, D_H, (rem >> 2) * 128, (rem & 3) * 128, (float*)dsm, tid);
            __threadfence();
            __syncthreads();
            if (tid == 0) atomicAdd(&g_cw1, 1);
        } else if (t < tb2) {                          // G1
            int t1 = t - tb1;
            int c = 0;
#pragma unroll
            for (int cc = 0; cc < C_CLUST; cc++) if (t1 >= g_g1s[cc + 1]) c = cc + 1;
            int rem = t1 - g_g1s[c];
            int m0 = (rem >> 2) * 128, n0 = (rem & 3) * 128;
            if (tid == 0) {
                SPIN_WAIT(ldacq(&g_gather_done) < ng || ldacq(&g_cw1) < NCONV_W1);
            }
            __syncthreads();
            gemm_tile<false>(g_Xg, g_W1t + (size_t)c * D_H * D_IN, b1 + c * D_H, nullptr,
                             D_IN, g_count[c], g_off[c], m0, n0, dsm, s_col, tid);
            __threadfence();
            __syncthreads();
            if (tid == 0) atomicAdd(&g_g1_done[c], 1);
        } else if (t < tb3) {                          // conv W2 (overlaps G1)
            int tc = t - tb2;
            int c = tc >> 4, rem = tc & 15;
            conv_tile(W2 + (size_t)c * D_H * D_H, g_W2t + (size_t)c * D_H * D_H,
                      D_H, D_H, (rem >> 2) * 128, (rem & 3) * 128, (float*)dsm, tid);
            __threadfence();
            __syncthreads();
            if (tid == 0) atomicAdd(&g_cw2, 1);
        } else if (t < tb4) {                          // G2
            int t2 = t - tb3;
            int c = 0;
#pragma unroll
            for (int cc = 0; cc < C_CLUST; cc++) if (t2 >= g_g2s[cc + 1]) c = cc + 1;
            int rem = t2 - g_g2s[c];
            int m0 = (rem >> 2) * 128, n0 = (rem & 3) * 128;
            int target = g_g1s[c + 1] - g_g1s[c];
            if (tid == 0) {
                SPIN_WAIT(ldacq(&g_g1_done[c]) < target || ldacq(&g_cw2) < NCONV_W2);
            }
            __syncthreads();
            gemm_tile<true>(g_H1, g_W2t + (size_t)c * D_H * D_H, b2 + c * D_H,
                            g_pool + c * D_H, D_H, g_count[c], g_off[c], m0, n0, dsm, s_col, tid);
            __threadfence();
            __syncthreads();
            if (tid == 0) atomicAdd(&g_g2_done[c], 1);
        } else if (t < tb5) {                          // E1 per (cluster, col-block)
            int idx = t - tb4;
            int c = idx >> 4, i = idx & 15;
            int target = g_g2s[c + 1] - g_g2s[c];
            if (tid == 0) { SPIN_WAIT(ldacq(&g_g2_done[c]) < target); }
            __syncthreads();
            e1_task(c, i, Wfc, bfc, dsm, tid);
        } else if (t < tb6) {                          // E2 per (cluster, attcol-block)
            int idx = t - tb5;
            int c = idx >> 3, i = idx & 7;
            if (tid == 0) { SPIN_WAIT(ldacq(&g_e1c[c]) < 16); }
            __syncthreads();
            e2_task(c, i, Wa, ba, Wb, bb, Wcs, dsm, tid);
        } else if (t < tb7) {                          // E3
            if (tid == 0) { SPIN_WAIT(ldacq(&g_e2) < NE2T); }
            __syncthreads();
            e3_task(t - tb6, bcs, Wr, br, dsm, tid);
        } else {                                       // E4
            if (tid == 0) { SPIN_WAIT(ldacq(&g_e3) < NE3); }
            __syncthreads();
            e4_task(Wcls, bcls, out, out_size, dsm, tid);
        }
        __syncthreads();
    }
}

// ---------------- launch ----------------
extern "C" void kernel_launch(void* const* d_in, const int* in_sizes, int n_in,
                              void* d_out, int out_size) {
    const float* x    = (const float*)d_in[0];
    const void*  cid  = d_in[1];
    const float* W1   = (const float*)d_in[2];
    const float* b1   = (const float*)d_in[3];
    const float* W2   = (const float*)d_in[4];
    const float* b2   = (const float*)d_in[5];
    const float* Wfc  = (const float*)d_in[6];
    const float* bfc  = (const float*)d_in[7];
    const float* Wa   = (const float*)d_in[8];
    const float* ba   = (const float*)d_in[9];
    const float* Wb   = (const float*)d_in[10];
    const float* bb   = (const float*)d_in[11];
    const float* Wc_  = (const float*)d_in[12];
    const float* bc_  = (const float*)d_in[13];
    const float* Wr   = (const float*)d_in[14];
    const float* br   = (const float*)d_in[15];
    const float* Wcls = (const float*)d_in[16];
    const float* bcls = (const float*)d_in[17];

    int n = in_sizes[0] / D_IN;

    static int nsm = 0;
    if (!nsm) {
        cudaDeviceProp prop;
        cudaGetDeviceProperties(&prop, 0);
        nsm = prop.multiProcessorCount;
        cudaFuncSetAttribute(k_mega, cudaFuncAttributeMaxDynamicSharedMemorySize, SMEM_SZ);
    }

    k_reset<<<1, 512>>>();                                     // 1
    k_count<<<(n + 255) / 256, 256>>>(cid, n);                 // 2
    k_offsets<<<1, 32>>>(n);                                   // 3
    k_mega<<<2 * nsm, 256, SMEM_SZ>>>(                         // 4  <- ncu target
        x, cid, n, W1, W2, b1, b2, Wfc, bfc, Wa, ba, Wb, bb,
        Wc_, bc_, Wr, br, Wcls, bcls, (float*)d_out, out_size);
}

// round 15
// speedup vs baseline: 1.7756x; 1.0799x over previous
#include <cuda_runtime.h>
#include <cuda_bf16.h>
#include <math.h>
#include <stdint.h>

#define C_CLUST 10
#define D_IN    1024
#define D_H     512
#define D_ATT   256
#define N_CLS   4
#define N_MAX   10000
#define NPAD    128

#define KC 64
#define ROWB 144                            // smem row stride bytes (72 bf16)
#define A_BYTES (128 * ROWB)                // 18432
#define STAGE_BYTES (2 * A_BYTES)           // 36864
#define SMEM_SZ (2 * STAGE_BYTES)           // 73728

#define NCONV_W1 320                        // 10 * 32 tiles
#define NCONV_W2 160                        // 10 * 16 tiles
#define GROWS    32
#define NE1T     160                        // E1: (cluster, 32-col block)
#define NE2T     80                         // E2: (cluster, 32-attcol block)
#define NE3      8                          // E3: 32-col blocks of rho
#define MBMAX    80                         // max m-blocks per cluster

// ---------------- scratch ----------------
__device__ int   g_count[C_CLUST];
__device__ int   g_off[C_CLUST];
__device__ int   g_cursor[C_CLUST];
__device__ int   g_g1s[C_CLUST + 1];
__device__ int   g_g2s[C_CLUST + 1];
__device__ int   g_ng;
__device__ int   g_tb[8];                   // task boundaries
__device__ int   g_ntask;
__device__ int   g_task;
__device__ int   g_gather_done;
__device__ int   g_cw1c[C_CLUST];           // conv W1 tiles done per cluster
__device__ int   g_cw2c[C_CLUST];           // conv W2 tiles done per cluster
__device__ int   g_g1_mb[C_CLUST * MBMAX];  // G1 tiles done per (cluster, m-block)
__device__ int   g_g2_done[C_CLUST];
__device__ int   g_e1c[C_CLUST];
__device__ int   g_e2, g_e3;
__device__ __nv_bfloat16 g_Xg[(size_t)(N_MAX + NPAD) * D_IN];
__device__ __nv_bfloat16 g_H1[(size_t)(N_MAX + NPAD) * D_H];
__device__ __nv_bfloat16 g_W1t[(size_t)C_CLUST * D_H * D_IN];
__device__ __nv_bfloat16 g_W2t[(size_t)C_CLUST * D_H * D_H];
__device__ float g_pool[C_CLUST * D_H];
__device__ float g_hbuf[C_CLUST * D_H];
__device__ float g_AccA[C_CLUST];
__device__ float g_hr[D_ATT];

__device__ __forceinline__ int detect64(const void* cid) {
    const int* p = (const int*)cid;
    int allz = 1;
#pragma unroll
    for (int i = 1; i < 32; i += 2) if (p[i] != 0) allz = 0;
    return allz;
}
__device__ __forceinline__ int get_cid(const void* cid, int n, int is64) {
    if (is64) return (int)((const long long*)cid)[n];
    return ((const int*)cid)[n];
}
__device__ __forceinline__ uint32_t smem_u32(const void* p) {
    uint32_t a;
    asm("{ .reg .u64 t; cvta.to.shared.u64 t, %1; cvt.u32.u64 %0, t; }" : "=r"(a) : "l"(p));
    return a;
}
__device__ __forceinline__ void cp16(uint32_t smem, const void* gmem) {
    asm volatile("cp.async.cg.shared.global [%0], [%1], 16;" :: "r"(smem), "l"(gmem));
}
__device__ __forceinline__ void ldsm4(uint32_t& r0, uint32_t& r1, uint32_t& r2, uint32_t& r3,
                                      uint32_t addr) {
    asm volatile("ldmatrix.sync.aligned.m8n8.x4.shared.b16 {%0,%1,%2,%3}, [%4];"
                 : "=r"(r0), "=r"(r1), "=r"(r2), "=r"(r3) : "r"(addr));
}
__device__ __forceinline__ void mma_bf16(float c[4], uint32_t a0, uint32_t a1, uint32_t a2,
                                         uint32_t a3, uint32_t b0, uint32_t b1) {
    asm volatile(
        "mma.sync.aligned.m16n8k16.row.col.f32.bf16.bf16.f32 "
        "{%0,%1,%2,%3}, {%4,%5,%6,%7}, {%8,%9}, {%0,%1,%2,%3};\n"
        : "+f"(c[0]), "+f"(c[1]), "+f"(c[2]), "+f"(c[3])
        : "r"(a0), "r"(a1), "r"(a2), "r"(a3), "r"(b0), "r"(b1));
}
__device__ __forceinline__ int ldacq(const int* p) {
    int v; asm volatile("ld.acquire.gpu.s32 %0, [%1];" : "=r"(v) : "l"(p)); return v;
}
#define SPIN_WAIT(cond) do {                      \
    int _sl = 64;                                 \
    while (cond) {                                \
        __nanosleep(_sl);                         \
        if (_sl < 512) _sl <<= 1;                 \
    }                                             \
} while (0)

// ---------------- prep kernels ----------------
__global__ void k_reset() {
    int t = threadIdx.x;   // 512
    for (int i = t; i < C_CLUST * D_H; i += 512) g_pool[i] = 0.f;
    for (int i = t; i < C_CLUST * MBMAX; i += 512) g_g1_mb[i] = 0;
    if (t < C_CLUST) {
        g_count[t] = 0; g_cursor[t] = 0; g_g2_done[t] = 0;
        g_cw1c[t] = 0; g_cw2c[t] = 0;
        g_e1c[t] = 0; g_AccA[t] = 0.f;
    }
    if (t == 0) {
        g_task = 0; g_gather_done = 0; g_e2 = 0; g_e3 = 0;
    }
}

__global__ void k_count(const void* __restrict__ cid, int n) {
    __shared__ int s[C_CLUST];
    int t = threadIdx.x;
    int is64 = detect64(cid);
    if (t < C_CLUST) s[t] = 0;
    __syncthreads();
    int i = blockIdx.x * blockDim.x + t;
    if (i < n) atomicAdd(&s[get_cid(cid, i, is64)], 1);
    __syncthreads();
    if (t < C_CLUST && s[t]) atomicAdd(&g_count[t], s[t]);
}

__global__ void k_offsets(int n) {
    if (threadIdx.x == 0) {
        int o = 0, g1 = 0, g2 = 0;
        for (int c = 0; c < C_CLUST; c++) {
            g_off[c] = o; o += g_count[c];
            int mt = (g_count[c] + 127) >> 7;
            g_g1s[c] = g1; g1 += 4 * mt;
            g_g2s[c] = g2; g2 += 4 * mt;
        }
        g_g1s[C_CLUST] = g1;
        g_g2s[C_CLUST] = g2;
        int ng = (n + GROWS - 1) / GROWS;
        g_ng = ng;
        g_tb[0] = ng;                         // end gather
        g_tb[1] = g_tb[0] + NCONV_W1;         // end conv W1
        g_tb[2] = g_tb[1] + g1;               // end G1
        g_tb[3] = g_tb[2] + NCONV_W2;         // end conv W2
        g_tb[4] = g_tb[3] + g2;               // end G2
        g_tb[5] = g_tb[4] + NE1T;             // end E1
        g_tb[6] = g_tb[5] + NE2T;             // end E2
        g_tb[7] = g_tb[6] + NE3;              // end E3
        g_ntask = g_tb[7] + 1;                // + E4
    }
}

// ---------------- gather task ----------------
__device__ void gather_task(const float* __restrict__ x, const void* __restrict__ cid,
                            int n, int base, char* dsm, int tid) {
    int* slot = (int*)dsm;
    if (tid < GROWS) {
        int p = base + tid;
        int s = -1;
        if (p < n) {
            int is64 = detect64(cid);
            int c = get_cid(cid, p, is64);
            s = g_off[c] + atomicAdd(&g_cursor[c], 1);
        }
        slot[tid] = s;
    }
    __syncthreads();
    int r = tid >> 3, q = tid & 7;           // 8 threads per row
    int p = base + r;
    if (p < n) {
        int dst = slot[r];
        const float4* src = (const float4*)(x + (size_t)p * D_IN);
        uint2* d = (uint2*)(g_Xg + (size_t)dst * D_IN);
#pragma unroll 8
        for (int i = 0; i < 32; i++) {
            float4 v = src[i * 8 + q];
            __nv_bfloat162 lo = __floats2bfloat162_rn(v.x, v.y);
            __nv_bfloat162 hi = __floats2bfloat162_rn(v.z, v.w);
            uint2 u;
            u.x = *(uint32_t*)&lo;
            u.y = *(uint32_t*)&hi;
            d[i * 8 + q] = u;
        }
    }
    __threadfence();
    __syncthreads();
    if (tid == 0) atomicAdd(&g_gather_done, 1);
    __syncthreads();
}

// ---------------- conv tile: 128x128 transpose fp32 -> bf16 ----------------
__device__ void conv_tile(const float* __restrict__ src, __nv_bfloat16* __restrict__ dst,
                          int R, int C, int r0, int c0, float* sm, int tid) {
    int r = tid >> 1;
    int cb = (tid & 1) * 64;
    const float* s = src + (size_t)(r0 + r) * C + c0 + cb;
#pragma unroll
    for (int q = 0; q < 16; q++) {
        float4 v = *(const float4*)(s + q * 4);
        float* d = sm + r * 129 + cb + q * 4;
        d[0] = v.x; d[1] = v.y; d[2] = v.z; d[3] = v.w;
    }
    __syncthreads();
#pragma unroll
    for (int q = 0; q < 16; q++) {
        int lin = q * 256 + tid;
        int j = lin >> 5;
        int i4 = (lin & 31) * 4;
        float a0 = sm[(i4 + 0) * 129 + j];
        float a1 = sm[(i4 + 1) * 129 + j];
        float a2 = sm[(i4 + 2) * 129 + j];
        float a3 = sm[(i4 + 3) * 129 + j];
        __nv_bfloat162 lo = __floats2bfloat162_rn(a0, a1);
        __nv_bfloat162 hi = __floats2bfloat162_rn(a2, a3);
        uint2 u;
        u.x = *(uint32_t*)&lo;
        u.y = *(uint32_t*)&hi;
        *(uint2*)(dst + (size_t)(c0 + j) * R + r0 + i4) = u;
    }
    __syncthreads();
}

// ---------------- GEMM tile (validated 2-stage) ----------------
template <bool POOL>
__device__ __forceinline__ void gemm_tile(
    const __nv_bfloat16* __restrict__ Aglob, const __nv_bfloat16* __restrict__ Wc,
    const float* __restrict__ bias_c, float* __restrict__ pool_c,
    int K, int M, int seg, int m0, int n0, char* dsm, float* s_col, int tid) {

    uint32_t sbase = smem_u32(dsm);
    int lane = tid & 31;
    int w = tid >> 5;
    int wm = w & 1;
    int wn = w >> 1;
    int g = lane >> 2;
    int tig = lane & 3;
    int l7 = lane & 7, l8 = (lane >> 3) & 1, l16 = lane >> 4;

    float acc[4][4][4];
#pragma unroll
    for (int im = 0; im < 4; im++)
#pragma unroll
        for (int in = 0; in < 4; in++)
#pragma unroll
            for (int q = 0; q < 4; q++) acc[im][in][q] = 0.f;

    int ar = tid >> 1;
    int acs = (tid & 1) * 4;
    const __nv_bfloat16* Arow = Aglob + (size_t)(seg + m0 + ar) * K + acs * 8;
    const __nv_bfloat16* Brow = Wc + (size_t)(n0 + ar) * K + acs * 8;
    uint32_t a_sm = ar * ROWB + acs * 16;
    uint32_t b_sm = A_BYTES + a_sm;

    uint32_t a_frag = (uint32_t)(wm * 64 + l7 + 8 * l8) * ROWB + 16 * l16;
    uint32_t b_frag = A_BYTES + (uint32_t)(wn * 32 + l7 + 8 * l8) * ROWB + 16 * l16;

    int nch = K / KC;
    {
        uint32_t st = sbase;
#pragma unroll
        for (int q = 0; q < 4; q++) cp16(st + a_sm + q * 16, Arow + q * 8);
#pragma unroll
        for (int q = 0; q < 4; q++) cp16(st + b_sm + q * 16, Brow + q * 8);
        asm volatile("cp.async.commit_group;" ::: "memory");
    }

    for (int c = 0; c < nch; c++) {
        if (c + 1 < nch) {
            uint32_t st = sbase + ((c + 1) & 1) * STAGE_BYTES;
            const __nv_bfloat16* ap = Arow + (c + 1) * KC;
            const __nv_bfloat16* bp = Brow + (c + 1) * KC;
#pragma unroll
            for (int q = 0; q < 4; q++) cp16(st + a_sm + q * 16, ap + q * 8);
#pragma unroll
            for (int q = 0; q < 4; q++) cp16(st + b_sm + q * 16, bp + q * 8);
            asm volatile("cp.async.commit_group;" ::: "memory");
            asm volatile("cp.async.wait_group 1;" ::: "memory");
        } else {
            asm volatile("cp.async.wait_group 0;" ::: "memory");
        }
        __syncthreads();

        uint32_t stb = sbase + (c & 1) * STAGE_BYTES;
#pragma unroll
        for (int ks = 0; ks < 4; ks++) {
            uint32_t koff = ks * 32;
            uint32_t bfr[2][4];
#pragma unroll
            for (int p = 0; p < 2; p++)
                ldsm4(bfr[p][0], bfr[p][1], bfr[p][2], bfr[p][3],
                      stb + b_frag + p * (16 * ROWB) + koff);
            uint32_t afr[4][4];
#pragma unroll
            for (int im = 0; im < 4; im++)
                ldsm4(afr[im][0], afr[im][1], afr[im][2], afr[im][3],
                      stb + a_frag + im * (16 * ROWB) + koff);
#pragma unroll
            for (int im = 0; im < 4; im++) {
#pragma unroll
                for (int p = 0; p < 2; p++) {
                    mma_bf16(acc[im][2 * p],     afr[im][0], afr[im][1], afr[im][2], afr[im][3],
                             bfr[p][0], bfr[p][2]);
                    mma_bf16(acc[im][2 * p + 1], afr[im][0], afr[im][1], afr[im][2], afr[im][3],
                             bfr[p][1], bfr[p][3]);
                }
            }
        }
        __syncthreads();
    }

    const float* bp = bias_c + n0;

    if (!POOL) {
#pragma unroll
        for (int im = 0; im < 4; im++) {
            int rg = m0 + wm * 64 + im * 16 + g;
            int rg8 = rg + 8;
#pragma unroll
            for (int in = 0; in < 4; in++) {
                int col = wn * 32 + in * 8 + 2 * tig;
                float b0v = bp[col], b1v = bp[col + 1];
                if (rg < M) {
                    __nv_bfloat162 v = __floats2bfloat162_rn(
                        fmaxf(acc[im][in][0] + b0v, 0.f), fmaxf(acc[im][in][1] + b1v, 0.f));
                    *(__nv_bfloat162*)&g_H1[(size_t)(seg + rg) * D_H + n0 + col] = v;
                }
                if (rg8 < M) {
                    __nv_bfloat162 v = __floats2bfloat162_rn(
                        fmaxf(acc[im][in][2] + b0v, 0.f), fmaxf(acc[im][in][3] + b1v, 0.f));
                    *(__nv_bfloat162*)&g_H1[(size_t)(seg + rg8) * D_H + n0 + col] = v;
                }
            }
        }
    } else {
        if (tid < 128) s_col[tid] = 0.f;
        __syncthreads();
#pragma unroll
        for (int in = 0; in < 4; in++) {
            int col = wn * 32 + in * 8 + 2 * tig;
            float b0v = bp[col], b1v = bp[col + 1];
            float px = 0.f, py = 0.f;
#pragma unroll
            for (int im = 0; im < 4; im++) {
                int rg = m0 + wm * 64 + im * 16 + g;
                if (rg < M) {
                    px += fmaxf(acc[im][in][0] + b0v, 0.f);
                    py += fmaxf(acc[im][in][1] + b1v, 0.f);
                }
                if (rg + 8 < M) {
                    px += fmaxf(acc[im][in][2] + b0v, 0.f);
                    py += fmaxf(acc[im][in][3] + b1v, 0.f);
                }
            }
            atomicAdd(&s_col[col], px);
            atomicAdd(&s_col[col + 1], py);
        }
        __syncthreads();
        if (tid < 128) atomicAdd(&pool_c[n0 + tid], s_col[tid]);
    }
}

// ---------------- E1: fc, one (cluster, 32-col) task ----------------
__device__ void e1_task(int c, int i, const float* __restrict__ Wfc,
                        const float* __restrict__ bfc, char* dsm, int tid) {
    float* ph = (float*)dsm;          // 512
    float* s_p = ph + D_H;            // 256
    int j0 = i * 32;
    int j = tid & 31, ks = tid >> 5;
    float inv = 1.f / (float)max(g_count[c], 1);
    for (int q = tid; q < D_H; q += 256) ph[q] = g_pool[c * D_H + q] * inv;
    __syncthreads();
    float p = 0.f;
#pragma unroll 8
    for (int k = ks * 64; k < ks * 64 + 64; k++)
        p += ph[k] * Wfc[k * D_H + j0 + j];
    s_p[ks * 32 + j] = p;
    __syncthreads();
    if (tid < 32) {
        float s = 0.f;
#pragma unroll
        for (int q = 0; q < 8; q++) s += s_p[q * 32 + tid];
        g_hbuf[c * D_H + j0 + tid] = fmaxf(s + bfc[j0 + tid], 0.f);
    }
    __threadfence();
    __syncthreads();
    if (tid == 0) atomicAdd(&g_e1c[c], 1);
    __syncthreads();
}

// ---------------- E2: gated attention, one (cluster, 32-attcol) task ----------------
__device__ void e2_task(int c, int i, const float* __restrict__ Wa, const float* __restrict__ ba,
                        const float* __restrict__ Wb, const float* __restrict__ bb,
                        const float* __restrict__ Wcs, char* dsm, int tid) {
    float* hc = (float*)dsm;          // 512
    float* s_sa = hc + D_H;           // 256
    float* s_sb = s_sa + 256;         // 256
    int col0 = i * 32;
    int col = tid & 31, ks = tid >> 5;
    for (int q = tid; q < D_H; q += 256) hc[q] = g_hbuf[c * D_H + q];
    __syncthreads();
    float sa = 0.f, sb = 0.f;
#pragma unroll 8
    for (int k = ks * 64; k < ks * 64 + 64; k++) {
        float hv = hc[k];
        sa += hv * Wa[k * D_ATT + col0 + col];
        sb += hv * Wb[k * D_ATT + col0 + col];
    }
    s_sa[ks * 32 + col] = sa;
    s_sb[ks * 32 + col] = sb;
    __syncthreads();
    if (tid < 32) {
        float ta = 0.f, tb = 0.f;
#pragma unroll
        for (int q = 0; q < 8; q++) { ta += s_sa[q * 32 + tid]; tb += s_sb[q * 32 + tid]; }
        float gate = tanhf(ta + ba[col0 + tid]) *
                     (1.f / (1.f + expf(-(tb + bb[col0 + tid]))));
        float part = gate * Wcs[col0 + tid];
#pragma unroll
        for (int off = 16; off > 0; off >>= 1)
            part += __shfl_down_sync(0xffffffff, part, off);
        if (tid == 0) atomicAdd(&g_AccA[c], part);
    }
    __threadfence();
    __syncthreads();
    if (tid == 0) atomicAdd(&g_e2, 1);
    __syncthreads();
}

// ---------------- E3: softmax + h_path + rho (32-col block) ----------------
__device__ void e3_task(int i, const float* __restrict__ bcs,
                        const float* __restrict__ Wr, const float* __restrict__ br,
                        char* dsm, int tid) {
    float* A = (float*)dsm;           // 16
    float* hp = A + 16;               // 512
    float* s_p = hp + D_H;            // 256
    int j0 = i * 32;
    if (tid == 0) {
        float m = -1e30f;
        float araw[C_CLUST];
        for (int c = 0; c < C_CLUST; c++) { araw[c] = g_AccA[c] + bcs[0]; m = fmaxf(m, araw[c]); }
        float s = 0.f;
        for (int c = 0; c < C_CLUST; c++) { A[c] = expf(araw[c] - m); s += A[c]; }
        float inv = 1.f / s;
        for (int c = 0; c < C_CLUST; c++) A[c] *= inv;
    }
    __syncthreads();
    for (int k = tid; k < D_H; k += 256) {
        float s = 0.f;
#pragma unroll
        for (int c = 0; c < C_CLUST; c++) s += A[c] * g_hbuf[c * D_H + k];
        hp[k] = s;
    }
    __syncthreads();
    int j = tid & 31, ks = tid >> 5;
    float p = 0.f;
#pragma unroll 8
    for (int k = ks * 64; k < ks * 64 + 64; k++)
        p += hp[k] * Wr[k * D_ATT + j0 + j];
    s_p[ks * 32 + j] = p;
    __syncthreads();
    if (tid < 32) {
        float s = 0.f;
#pragma unroll
        for (int q = 0; q < 8; q++) s += s_p[q * 32 + tid];
        g_hr[j0 + tid] = fmaxf(s + br[j0 + tid], 0.f);
    }
    __threadfence();
    __syncthreads();
    if (tid == 0) atomicAdd(&g_e3, 1);
    __syncthreads();
}

// ---------------- E4: classifier + softmax + argmax + output ----------------
__device__ void e4_task(const float* __restrict__ Wcls, const float* __restrict__ bcls,
                        float* __restrict__ out, int out_size, char* dsm, int tid) {
    float* hr = (float*)dsm;          // 256
    float* red = hr + 256;            // 256
    float* lg = red + 256;            // 4
    hr[tid] = g_hr[tid];
    __syncthreads();
    for (int i = 0; i < N_CLS; i++) {
        red[tid] = hr[tid] * Wcls[tid * N_CLS + i];
        __syncthreads();
        for (int s = 128; s > 0; s >>= 1) {
            if (tid < s) red[tid] += red[tid + s];
            __syncthreads();
        }
        if (tid == 0) lg[i] = red[0] + bcls[i];
        __syncthreads();
    }
    if (tid == 0) {
        float m = lg[0];
        int am = 0;
        for (int i = 1; i < N_CLS; i++) if (lg[i] > m) { m = lg[i]; am = i; }
        float e[N_CLS], s = 0.f;
        for (int i = 0; i < N_CLS; i++) { e[i] = expf(lg[i] - m); s += e[i]; }
        float vals[9];
        for (int i = 0; i < N_CLS; i++) vals[i] = lg[i];
        for (int i = 0; i < N_CLS; i++) vals[4 + i] = e[i] / s;
        vals[8] = (float)am;
        for (int i = 0; i < out_size; i++) out[i] = (i < 9) ? vals[i] : 0.f;
    }
    __syncthreads();
}

// ---------------- persistent mega kernel ----------------
__global__ void __launch_bounds__(256, 2)
k_mega(const float* __restrict__ x, const void* __restrict__ cid, int n,
       const float* __restrict__ W1, const float* __restrict__ W2,
       const float* __restrict__ b1, const float* __restrict__ b2,
       const float* __restrict__ Wfc, const float* __restrict__ bfc,
       const float* __restrict__ Wa, const float* __restrict__ ba,
       const float* __restrict__ Wb, const float* __restrict__ bb,
       const float* __restrict__ Wcs, const float* __restrict__ bcs,
       const float* __restrict__ Wr, const float* __restrict__ br,
       const float* __restrict__ Wcls, const float* __restrict__ bcls,
       float* __restrict__ out, int out_size) {
    extern __shared__ char dsm[];
    __shared__ float s_col[128];
    __shared__ int s_task;
    int tid = threadIdx.x;

    int ng = g_ng;
    int tb0 = g_tb[0], tb1 = g_tb[1], tb2 = g_tb[2], tb3 = g_tb[3];
    int tb4 = g_tb[4], tb5 = g_tb[5], tb6 = g_tb[6], tb7 = g_tb[7];
    int ntask = g_ntask;

    for (;;) {
        if (tid == 0) s_task = atomicAdd(&g_task, 1);
        __syncthreads();
        int t = s_task;
        if (t >= ntask) break;

        if (t < tb0) {
            gather_task(x, cid, n, t * GROWS, dsm, tid);
        } else if (t < tb1) {                          // conv W1 (32 tiles/cluster)
            int tc = t - tb0;
            int c = tc >> 5, rem = tc & 31;
            conv_tile(W1 + (size_t)c * D_IN * D_H, g_W1t + (size_t)c * D_H * D_IN,
                      D_IN, D_H, (rem >> 2) * 128, (rem & 3) * 128, (float*)dsm, tid);
            __threadfence();
            __syncthreads();
            if (tid == 0) atomicAdd(&g_cw1c[c], 1);
        } else if (t < tb2) {                          // G1
            int t1 = t - tb1;
            int c = 0;
#pragma unroll
            for (int cc = 0; cc < C_CLUST; cc++) if (t1 >= g_g1s[cc + 1]) c = cc + 1;
            int rem = t1 - g_g1s[c];
            int mb = rem >> 2;
            int m0 = mb * 128, n0 = (rem & 3) * 128;
            if (tid == 0) {
                SPIN_WAIT(ldacq(&g_gather_done) < ng || ldacq(&g_cw1c[c]) < 32);
            }
            __syncthreads();
            gemm_tile<false>(g_Xg, g_W1t + (size_t)c * D_H * D_IN, b1 + c * D_H, nullptr,
                             D_IN, g_count[c], g_off[c], m0, n0, dsm, s_col, tid);
            __threadfence();
            __syncthreads();
            if (tid == 0) atomicAdd(&g_g1_mb[c * MBMAX + mb], 1);
        } else if (t < tb3) {                          // conv W2 (16 tiles/cluster)
            int tc = t - tb2;
            int c = tc >> 4, rem = tc & 15;
            conv_tile(W2 + (size_t)c * D_H * D_H, g_W2t + (size_t)c * D_H * D_H,
                      D_H, D_H, (rem >> 2) * 128, (rem & 3) * 128, (float*)dsm, tid);
            __threadfence();
            __syncthreads();
            if (tid == 0) atomicAdd(&g_cw2c[c], 1);
        } else if (t < tb4) {                          // G2 (fine-gated per m-block)
            int t2 = t - tb3;
            int c = 0;
#pragma unroll
            for (int cc = 0; cc < C_CLUST; cc++) if (t2 >= g_g2s[cc + 1]) c = cc + 1;
            int rem = t2 - g_g2s[c];
            int mb = rem >> 2;
            int m0 = mb * 128, n0 = (rem & 3) * 128;
            if (tid == 0) {
                SPIN_WAIT(ldacq(&g_g1_mb[c * MBMAX + mb]) < 4 || ldacq(&g_cw2c[c]) < 16);
            }
            __syncthreads();
            gemm_tile<true>(g_H1, g_W2t + (size_t)c * D_H * D_H, b2 + c * D_H,
                            g_pool + c * D_H, D_H, g_count[c], g_off[c], m0, n0, dsm, s_col, tid);
            __threadfence();
            __syncthreads();
            if (tid == 0) atomicAdd(&g_g2_done[c], 1);
        } else if (t < tb5) {                          // E1 per (cluster, col-block)
            int idx = t - tb4;
            int c = idx >> 4, i = idx & 15;
            int target = g_g2s[c + 1] - g_g2s[c];
            if (tid == 0) { SPIN_WAIT(ldacq(&g_g2_done[c]) < target); }
            __syncthreads();
            e1_task(c, i, Wfc, bfc, dsm, tid);
        } else if (t < tb6) {                          // E2 per (cluster, attcol-block)
            int idx = t - tb5;
            int c = idx >> 3, i = idx & 7;
            if (tid == 0) { SPIN_WAIT(ldacq(&g_e1c[c]) < 16); }
            __syncthreads();
            e2_task(c, i, Wa, ba, Wb, bb, Wcs, dsm, tid);
        } else if (t < tb7) {                          // E3
            if (tid == 0) { SPIN_WAIT(ldacq(&g_e2) < NE2T); }
            __syncthreads();
            e3_task(t - tb6, bcs, Wr, br, dsm, tid);
        } else {                                       // E4
            if (tid == 0) { SPIN_WAIT(ldacq(&g_e3) < NE3); }
            __syncthreads();
            e4_task(Wcls, bcls, out, out_size, dsm, tid);
        }
        __syncthreads();
    }
}

// ---------------- launch ----------------
extern "C" void kernel_launch(void* const* d_in, const int* in_sizes, int n_in,
                              void* d_out, int out_size) {
    const float* x    = (const float*)d_in[0];
    const void*  cid  = d_in[1];
    const float* W1   = (const float*)d_in[2];
    const float* b1   = (const float*)d_in[3];
    const float* W2   = (const float*)d_in[4];
    const float* b2   = (const float*)d_in[5];
    const float* Wfc  = (const float*)d_in[6];
    const float* bfc  = (const float*)d_in[7];
    const float* Wa   = (const float*)d_in[8];
    const float* ba   = (const float*)d_in[9];
    const float* Wb   = (const float*)d_in[10];
    const float* bb   = (const float*)d_in[11];
    const float* Wc_  = (const float*)d_in[12];
    const float* bc_  = (const float*)d_in[13];
    const float* Wr   = (const float*)d_in[14];
    const float* br   = (const float*)d_in[15];
    const float* Wcls = (const float*)d_in[16];
    const float* bcls = (const float*)d_in[17];

    int n = in_sizes[0] / D_IN;

    static int nsm = 0;
    if (!nsm) {
        cudaDeviceProp prop;
        cudaGetDeviceProperties(&prop, 0);
        nsm = prop.multiProcessorCount;
        cudaFuncSetAttribute(k_mega, cudaFuncAttributeMaxDynamicSharedMemorySize, SMEM_SZ);
    }

    k_reset<<<1, 512>>>();                                     // 1
    k_count<<<(n + 255) / 256, 256>>>(cid, n);                 // 2
    k_offsets<<<1, 32>>>(n);                                   // 3
    k_mega<<<2 * nsm, 256, SMEM_SZ>>>(                         // 4  <- ncu target
        x, cid, n, W1, W2, b1, b2, Wfc, bfc, Wa, ba, Wb, bb,
        Wc_, bc_, Wr, br, Wcls, bcls, (float*)d_out, out_size);
}